// round 10
// baseline (speedup 1.0000x reference)
#include <cuda_runtime.h>
#include <cuda_fp16.h>
#include <math.h>
#include <stdint.h>

#define TT 4
#define NN 50000
#define DD 256
#define HH 8
#define RR 4
#define EE 200000
#define DK 32
#define D4 1024
#define K2Q (2*DD)    // 512
#define K2F (2*D4)    // 2048

// ---------------- scratch (device globals; allocation is forbidden) ----------------
__device__ __align__(16) float    g_Q[(size_t)TT*NN*DD];
__device__ __align__(16) float    g_kv1[(size_t)NN*1024];   // st=1: [k_r0|v_r0|k_r3|v_r3]
__device__ __align__(16) float    g_kv2[(size_t)NN*512];    // st=2: [k_r1|v_r1]
__device__ __align__(16) float    g_kv3[(size_t)NN*512];    // st=3: [k_r2|v_r2]
__device__ __align__(16) float    g_agg[(size_t)TT*NN*DD];
__device__ __align__(16) float    g_h[(size_t)TT*NN*DD];
__device__ __align__(16) float    g_f2[(size_t)TT*NN*DD];
__device__ __align__(16) float    g_logits[(size_t)RR*EE*HH];
__device__ __align__(16) float    g_p[(size_t)RR*EE*HH];
__device__ __align__(16) unsigned g_m[(size_t)RR*NN*HH];
__device__ __align__(16) float    g_z[(size_t)RR*NN*HH];
__device__ __align__(16) float    g_Wkr[RR*DD*DD];
__device__ __align__(16) float    g_Wvr[RR*DD*DD];
__device__ __align__(16) float    g_bkv1[1024];
__device__ __align__(16) float    g_bkv2[512];
__device__ __align__(16) float    g_bkv3[512];
// fp16 split-pair operands (A=[hi|lo], B=[hi|hi])
__device__ __align__(256) __half g_x2[(size_t)TT*NN*K2Q];
__device__ __align__(256) __half g_h2[(size_t)TT*NN*K2Q];
__device__ __align__(256) __half g_fh[(size_t)TT*NN*K2F];
__device__ __align__(256) __half g_wq2[(size_t)TT*DD*K2Q];
__device__ __align__(256) __half g_wkv1[(size_t)1024*K2Q];
__device__ __align__(256) __half g_wkv2[(size_t)512*K2Q];
__device__ __align__(256) __half g_wkv3[(size_t)512*K2Q];
__device__ __align__(256) __half g_w12[(size_t)TT*D4*K2Q];
__device__ __align__(256) __half g_w22[(size_t)TT*DD*K2F];

// ---------------- small helpers ----------------
__device__ __forceinline__ unsigned fenc(float f) {
    unsigned u = __float_as_uint(f);
    return (u & 0x80000000u) ? ~u : (u | 0x80000000u);
}
__device__ __forceinline__ float fdec(unsigned u) {
    unsigned b = (u & 0x80000000u) ? (u & 0x7FFFFFFFu) : ~u;
    return __uint_as_float(b);
}
__device__ __forceinline__ uint32_t smem_u32(const void* p) {
    return (uint32_t)__cvta_generic_to_shared(p);
}
__device__ __forceinline__ void cp16(uint32_t d, const void* g, int sz) {
    asm volatile("cp.async.cg.shared.global [%0], [%1], 16, %2;"
                 :: "r"(d), "l"(g), "r"(sz));
}
__device__ __forceinline__ void cp_commit() {
    asm volatile("cp.async.commit_group;");
}
__device__ __forceinline__ void ldm_x4(uint32_t* r, uint32_t a) {
    asm volatile("ldmatrix.sync.aligned.m8n8.x4.shared.b16 {%0,%1,%2,%3}, [%4];"
                 : "=r"(r[0]), "=r"(r[1]), "=r"(r[2]), "=r"(r[3]) : "r"(a));
}
__device__ __forceinline__ void mma16816(float* c, const uint32_t* a,
                                         uint32_t b0, uint32_t b1) {
    asm volatile(
        "mma.sync.aligned.m16n8k16.row.col.f32.f16.f16.f32 "
        "{%0,%1,%2,%3}, {%4,%5,%6,%7}, {%8,%9}, {%0,%1,%2,%3};"
        : "+f"(c[0]), "+f"(c[1]), "+f"(c[2]), "+f"(c[3])
        : "r"(a[0]), "r"(a[1]), "r"(a[2]), "r"(a[3]), "r"(b0), "r"(b1));
}

// ---------------- mma.sync split-fp16 GEMM (hoisted addressing) ----------------
#define ROWB 80
#define STAGE_B (128*ROWB*2)
#define GSMEM_TOTAL (4*STAGE_B)

__global__ void __launch_bounds__(256, 2)
mma_gemm(const __half* __restrict__ A2, const __half* __restrict__ B2,
         const float* __restrict__ bias, float* __restrict__ Cout,
         __half* __restrict__ C2out,
         int M, int K2, int Nout,
         long long sA, long long sB, long long sBias, long long sC, int epi)
{
    extern __shared__ __align__(128) char smem[];
    const int t = blockIdx.z;
    A2 += (long long)t * sA;
    B2 += (long long)t * sB;
    bias += (long long)t * sBias;
    if (Cout)  Cout  += (long long)t * sC;
    if (C2out) C2out += (long long)t * (2LL * sC);

    const uint32_t sb = smem_u32(smem);
    const int tid = threadIdx.x;
    const int wid = tid >> 5;
    const int lane = tid & 31;
    const int wm = wid >> 2;
    const int wn = wid & 3;

    const int bm = blockIdx.x * 128;
    const int bn = blockIdx.y * 128;
    const int NC = K2 >> 5;

    // ---- hoisted cp.async addressing (each thread moves 2 A rows + 2 B rows) ----
    const int crow = tid >> 2;          // 0..63
    const int cc4  = tid & 3;           // 0..3 (16B segment)
    const __half* srcA0 = A2 + (long long)(bm + crow) * K2 + cc4 * 8;
    const __half* srcA1 = srcA0 + (long long)64 * K2;
    const __half* srcB0 = B2 + (long long)(bn + crow) * K2 + cc4 * 8;
    const __half* srcB1 = srcB0 + (long long)64 * K2;
    const int szA0 = (bm + crow      < M) ? 16 : 0;
    const int szA1 = (bm + crow + 64 < M) ? 16 : 0;
    const uint32_t dA0 = sb + crow * ROWB + cc4 * 16;
    const uint32_t dA1 = dA0 + 64 * ROWB;
    const uint32_t dB0 = dA0 + 128 * ROWB;
    const uint32_t dB1 = dB0 + 64 * ROWB;

    // ---- hoisted ldmatrix addressing (slot 0; add rolling offset in loop) ----
    uint32_t a_ld[2][4], b_ld[2][2];
#pragma unroll
    for (int kh = 0; kh < 2; kh++) {
        int col2 = (kh * 16 + ((lane >> 4) << 3)) * 2;
#pragma unroll
        for (int mi = 0; mi < 4; mi++)
            a_ld[kh][mi] = sb + (wm * 64 + mi * 16 + (lane & 15)) * ROWB + col2;
#pragma unroll
        for (int bi = 0; bi < 2; bi++)
            b_ld[kh][bi] = sb + 128 * ROWB + (wn * 32 + bi * 16 + (lane & 15)) * ROWB + col2;
    }

    float acc[4][4][4];
#pragma unroll
    for (int i = 0; i < 4; i++)
#pragma unroll
        for (int j = 0; j < 4; j++)
#pragma unroll
            for (int c = 0; c < 4; c++) acc[i][j][c] = 0.f;

    uint32_t wo = 0;   // write slot offset
#define LOADN do {                                              \
        cp16(dA0 + wo, srcA0, szA0); cp16(dA1 + wo, srcA1, szA1); \
        cp16(dB0 + wo, srcB0, 16);   cp16(dB1 + wo, srcB1, 16);   \
        cp_commit();                                              \
        srcA0 += 32; srcA1 += 32; srcB0 += 32; srcB1 += 32;       \
        wo += STAGE_B; if (wo == 4 * STAGE_B) wo = 0;             \
    } while (0)

    LOADN; LOADN; LOADN;

    uint32_t ro = 0;   // read slot offset
    for (int j = 0; j < NC; j++) {
        int wg = NC - 1 - j; if (wg > 2) wg = 2;
        if (wg == 2)      asm volatile("cp.async.wait_group 2;");
        else if (wg == 1) asm volatile("cp.async.wait_group 1;");
        else              asm volatile("cp.async.wait_group 0;");
        __syncthreads();
        if (j + 3 < NC) LOADN;

#pragma unroll
        for (int kh = 0; kh < 2; kh++) {
            uint32_t afr[4][4];
#pragma unroll
            for (int mi = 0; mi < 4; mi++) ldm_x4(afr[mi], a_ld[kh][mi] + ro);
            uint32_t bfr[2][4];
#pragma unroll
            for (int bi = 0; bi < 2; bi++) ldm_x4(bfr[bi], b_ld[kh][bi] + ro);
#pragma unroll
            for (int mi = 0; mi < 4; mi++)
#pragma unroll
                for (int ni = 0; ni < 4; ni++) {
                    uint32_t b0 = bfr[ni >> 1][ni & 1];
                    uint32_t b1 = bfr[ni >> 1][(ni & 1) + 2];
                    mma16816(acc[mi][ni], afr[mi], b0, b1);
                }
        }
        ro += STAGE_B; if (ro == 4 * STAGE_B) ro = 0;
    }
#undef LOADN

#pragma unroll
    for (int mi = 0; mi < 4; mi++) {
#pragma unroll
        for (int half = 0; half < 2; half++) {
            int row = bm + wm * 64 + mi * 16 + (lane >> 2) + half * 8;
            if (row >= M) continue;
#pragma unroll
            for (int ni = 0; ni < 4; ni++) {
                int col = bn + wn * 32 + ni * 8 + ((lane & 3) << 1);
                float v0 = acc[mi][ni][half * 2 + 0] + bias[col + 0];
                float v1 = acc[mi][ni][half * 2 + 1] + bias[col + 1];
                if (epi == 0) {
                    float2 v = make_float2(v0, v1);
                    *(float2*)&Cout[(long long)row * Nout + col] = v;
                } else {
                    v0 = 0.5f * v0 * (1.f + erff(v0 * 0.7071067811865476f));
                    v1 = 0.5f * v1 * (1.f + erff(v1 * 0.7071067811865476f));
                    __half h0 = __float2half_rn(v0);
                    __half h1 = __float2half_rn(v1);
                    __half l0 = __float2half_rn(v0 - __half2float(h0));
                    __half l1 = __float2half_rn(v1 - __half2float(h1));
                    __half2 hp, lp;
                    hp.x = h0; hp.y = h1;
                    lp.x = l0; lp.y = l1;
                    __half* rp = C2out + (long long)row * (2LL * Nout);
                    *(__half2*)&rp[col]        = hp;
                    *(__half2*)&rp[Nout + col] = lp;
                }
            }
        }
    }
}

// ---------------- weight fold (fp32) ----------------
__global__ void __launch_bounds__(256)
combine_w_kernel(const float* __restrict__ W, const float* __restrict__ Wrel,
                 float* __restrict__ outW, int st, int r)
{
    int idx = blockIdx.x * 256 + threadIdx.x;
    if (idx >= DD * DD) return;
    int d = idx >> 8;
    int c = idx & 255;
    int h = c >> 5, f = c & 31;
    const float* wrow = W + ((long long)st * DD + d) * DD + h * DK;
    const float* wr   = Wrel + ((long long)(r * HH + h) * DK) * DK + f;
    float s = 0.f;
#pragma unroll
    for (int k = 0; k < DK; k++) s = fmaf(wrow[k], wr[k * DK], s);
    outW[idx] = s;
}

__global__ void
combine_b_kernel(const float* __restrict__ b, const float* __restrict__ Wrel,
                 float* __restrict__ outb, int st, int r)
{
    int c = blockIdx.x * blockDim.x + threadIdx.x;
    if (c >= DD) return;
    int h = c >> 5, f = c & 31;
    const float* br = b + st * DD + h * DK;
    const float* wr = Wrel + ((long long)(r * HH + h) * DK) * DK + f;
    float s = 0.f;
#pragma unroll
    for (int k = 0; k < DK; k++) s = fmaf(br[k], wr[k * DK], s);
    outb[c] = s;
}

// ---------------- split-pair conversions (fp16) ----------------
__global__ void __launch_bounds__(256)
pair_a_kernel(const float* __restrict__ A, __half* __restrict__ A2,
              long long total, int K)
{
    long long i = (long long)blockIdx.x * 256 + threadIdx.x;
    if (i >= total) return;
    long long row = i / K;
    int k = (int)(i - row * K);
    float v = A[i];
    __half hi = __float2half_rn(v);
    __half lo = __float2half_rn(v - __half2float(hi));
    __half* r = A2 + row * (2LL * K);
    r[k] = hi; r[K + k] = lo;
}

__global__ void __launch_bounds__(256)
pair_w_kernel(const float* __restrict__ W, __half* __restrict__ W2,
              int K, int Nw)
{
    int i = blockIdx.x * 256 + threadIdx.x;
    if (i >= K * Nw) return;
    int k = i / Nw, n = i - k * Nw;
    __half hi = __float2half_rn(W[i]);
    __half* r = W2 + (long long)n * (2LL * K);
    r[k] = hi; r[K + k] = hi;
}

// ---------------- merged edge phase across all relations ----------------
__device__ __constant__ int c_dt[RR]    = {0, 0, 3, 3};
__device__ __constant__ int c_pitch[RR] = {1024, 512, 512, 1024};
__device__ __constant__ int c_koff[RR]  = {0, 0, 0, 512};
__device__ __constant__ int c_voff[RR]  = {256, 256, 256, 768};

__device__ __forceinline__ const float* kv_base(int r, const float* kv1,
                                                const float* kv2, const float* kv3) {
    return (r == 1) ? kv2 : (r == 2) ? kv3 : kv1;
}

__global__ void __launch_bounds__(256)
edge_dot_all(const float* __restrict__ Q, const float* __restrict__ kv1,
             const float* __restrict__ kv2, const float* __restrict__ kv3,
             const int* __restrict__ esrc, const int* __restrict__ edst,
             const float* __restrict__ rel_bias)
{
    const int warp = threadIdx.x >> 5;
    const int lane = threadIdx.x & 31;
    const int h = lane >> 2, q = lane & 3;
    long long ge = (long long)blockIdx.x * 8 + warp;
    if (ge >= (long long)RR * EE) return;
    int r = (int)(ge / EE);
    int s = esrc[ge];
    int d = edst[ge];
    const float* kb = kv_base(r, kv1, kv2, kv3);
    const float4* qp = (const float4*)&Q[((long long)c_dt[r] * NN + d) * DD + h * DK + q * 8];
    const float4* kp = (const float4*)&kb[(long long)s * c_pitch[r] + c_koff[r] + h * DK + q * 8];
    float4 q0 = qp[0], q1 = qp[1];
    float4 k0 = kp[0], k1 = kp[1];
    float acc = q0.x * k0.x + q0.y * k0.y + q0.z * k0.z + q0.w * k0.w
              + q1.x * k1.x + q1.y * k1.y + q1.z * k1.z + q1.w * k1.w;
    acc += __shfl_xor_sync(0xffffffffu, acc, 1);
    acc += __shfl_xor_sync(0xffffffffu, acc, 2);
    if (q == 0) {
        float lg = acc * 0.17677669529663687f + rel_bias[r];
        g_logits[ge * HH + h] = lg;
        atomicMax(&g_m[((long long)r * NN + d) * HH + h], fenc(lg));
    }
}

__global__ void __launch_bounds__(256)
seg_exp_all(const int* __restrict__ edst)
{
    long long i = (long long)blockIdx.x * 256 + threadIdx.x;
    if (i >= (long long)RR * EE * HH) return;
    long long ge = i >> 3;
    int h = (int)(i & 7);
    int r = (int)(ge / EE);
    int d = edst[ge];
    long long mz = ((long long)r * NN + d) * HH + h;
    float m = fdec(g_m[mz]);
    float p = expf(g_logits[i] - m);
    g_p[i] = p;
    atomicAdd(&g_z[mz], p);
}

// z -> 1/z (entries for nodes with no edges stay unused)
__global__ void __launch_bounds__(256)
recip_z_kernel()
{
    int i = blockIdx.x * 256 + threadIdx.x;
    if (i >= RR * NN * HH) return;
    float z = g_z[i];
    g_z[i] = (z != 0.f) ? (1.f / z) : 0.f;
}

__global__ void __launch_bounds__(256)
seg_msg_all(const int* __restrict__ esrc, const int* __restrict__ edst,
            const float* __restrict__ kv1, const float* __restrict__ kv2,
            const float* __restrict__ kv3, float* __restrict__ agg)
{
    long long i = (long long)blockIdx.x * 256 + threadIdx.x;   // RR*EE*64
    if (i >= (long long)RR * EE * 64) return;
    long long ge = i >> 6;
    int c = (int)(i & 63) * 4;
    int h = c >> 5;
    int r = (int)(ge / EE);
    int s = esrc[ge];
    int d = edst[ge];
    // g_z holds reciprocal -> multiply, no division
    float attn = g_p[ge * HH + h] * g_z[((long long)r * NN + d) * HH + h];
    const float* vb = kv_base(r, kv1, kv2, kv3);
    float4 v = *(const float4*)&vb[(long long)s * c_pitch[r] + c_voff[r] + c];
    float* dst = &agg[((long long)c_dt[r] * NN + d) * DD + c];
    asm volatile("red.global.add.v4.f32 [%0], {%1,%2,%3,%4};"
                 :: "l"(dst), "f"(attn * v.x), "f"(attn * v.y),
                    "f"(attn * v.z), "f"(attn * v.w)
                 : "memory");
}

// ---------------- layernorm(residual) [+ optional fp16-pair out] ----------------
__global__ void __launch_bounds__(256)
ln_kernel(const float* __restrict__ X, const float* __restrict__ Res,
          const float* __restrict__ G, const float* __restrict__ B,
          float* __restrict__ Out, __half* __restrict__ Out2)
{
    int row = blockIdx.x * 8 + (threadIdx.x >> 5);
    if (row >= TT * NN) return;
    int lane = threadIdx.x & 31;
    int t = row / NN;
    const float* xr = X + (long long)row * DD;
    const float* rr = Res + (long long)row * DD;
    float v[8];
    float sum = 0.f;
#pragma unroll
    for (int j = 0; j < 8; j++) {
        v[j] = xr[lane + 32 * j] + rr[lane + 32 * j];
        sum += v[j];
    }
#pragma unroll
    for (int o = 16; o > 0; o >>= 1) sum += __shfl_xor_sync(0xffffffffu, sum, o);
    float mu = sum * (1.f / 256.f);
    float var = 0.f;
#pragma unroll
    for (int j = 0; j < 8; j++) {
        float dlt = v[j] - mu;
        var = fmaf(dlt, dlt, var);
    }
#pragma unroll
    for (int o = 16; o > 0; o >>= 1) var += __shfl_xor_sync(0xffffffffu, var, o);
    float rstd = rsqrtf(var * (1.f / 256.f) + 1e-5f);
#pragma unroll
    for (int j = 0; j < 8; j++) {
        int c = lane + 32 * j;
        float y = (v[j] - mu) * rstd * G[t * DD + c] + B[t * DD + c];
        Out[(long long)row * DD + c] = y;
        if (Out2) {
            __half hi = __float2half_rn(y);
            __half lo = __float2half_rn(y - __half2float(hi));
            __half* r2 = Out2 + (long long)row * K2Q;
            r2[c] = hi; r2[DD + c] = lo;
        }
    }
}

// ---------------- launch ----------------
extern "C" void kernel_launch(void* const* d_in, const int* in_sizes, int n_in,
                              void* d_out, int out_size)
{
    const float* x       = (const float*)d_in[0];
    const int*   esrc    = (const int*)d_in[1];
    const int*   edst    = (const int*)d_in[2];
    const float* Wq      = (const float*)d_in[3];
    const float* bq      = (const float*)d_in[4];
    const float* Wk      = (const float*)d_in[5];
    const float* bk      = (const float*)d_in[6];
    const float* Wv      = (const float*)d_in[7];
    const float* bv      = (const float*)d_in[8];
    const float* W_attn  = (const float*)d_in[9];
    const float* W_msg   = (const float*)d_in[10];
    const float* relbias = (const float*)d_in[11];
    const float* ln1_g   = (const float*)d_in[12];
    const float* ln1_b   = (const float*)d_in[13];
    const float* ln2_g   = (const float*)d_in[14];
    const float* ln2_b   = (const float*)d_in[15];
    const float* ffn_w1  = (const float*)d_in[16];
    const float* ffn_b1  = (const float*)d_in[17];
    const float* ffn_w2  = (const float*)d_in[18];
    const float* ffn_b2  = (const float*)d_in[19];
    float* out = (float*)d_out;

    float *pQ, *pkv1, *pkv2, *pkv3, *pagg, *ph, *pf2, *pz;
    float *pWkr, *pWvr, *pbkv1, *pbkv2, *pbkv3;
    unsigned* pm;
    __half *px2, *ph2, *pfh, *pwq2, *pwkv1, *pwkv2, *pwkv3, *pw12, *pw22;
    cudaGetSymbolAddress((void**)&pQ, g_Q);
    cudaGetSymbolAddress((void**)&pkv1, g_kv1);
    cudaGetSymbolAddress((void**)&pkv2, g_kv2);
    cudaGetSymbolAddress((void**)&pkv3, g_kv3);
    cudaGetSymbolAddress((void**)&pagg, g_agg);
    cudaGetSymbolAddress((void**)&ph, g_h);
    cudaGetSymbolAddress((void**)&pf2, g_f2);
    cudaGetSymbolAddress((void**)&pm, g_m);
    cudaGetSymbolAddress((void**)&pz, g_z);
    cudaGetSymbolAddress((void**)&pWkr, g_Wkr);
    cudaGetSymbolAddress((void**)&pWvr, g_Wvr);
    cudaGetSymbolAddress((void**)&pbkv1, g_bkv1);
    cudaGetSymbolAddress((void**)&pbkv2, g_bkv2);
    cudaGetSymbolAddress((void**)&pbkv3, g_bkv3);
    cudaGetSymbolAddress((void**)&px2, g_x2);
    cudaGetSymbolAddress((void**)&ph2, g_h2);
    cudaGetSymbolAddress((void**)&pfh, g_fh);
    cudaGetSymbolAddress((void**)&pwq2, g_wq2);
    cudaGetSymbolAddress((void**)&pwkv1, g_wkv1);
    cudaGetSymbolAddress((void**)&pwkv2, g_wkv2);
    cudaGetSymbolAddress((void**)&pwkv3, g_wkv3);
    cudaGetSymbolAddress((void**)&pw12, g_w12);
    cudaGetSymbolAddress((void**)&pw22, g_w22);

    cudaFuncSetAttribute(mma_gemm, cudaFuncAttributeMaxDynamicSharedMemorySize, GSMEM_TOTAL);

    const long long sND = (long long)NN * DD;
    const long long sDD = (long long)DD * DD;
    const int stype[RR] = {1, 2, 3, 1};
    const int GMX = (NN + 127) / 128;   // 391
    const int CW = (DD * DD + 255) / 256;

    // launches 0-2: prereqs; launch index 3 = representative GEMM (profiled)
    {
        long long total = (long long)TT * NN * DD;
        pair_a_kernel<<<(unsigned)((total + 255) / 256), 256>>>(x, px2, total, DD);    // 0
    }
    pair_w_kernel<<<CW, 256>>>(Wq + 0 * sDD, pwq2 + 0LL * DD * K2Q, DD, DD);           // 1
    pair_w_kernel<<<CW, 256>>>(Wq + 3 * sDD, pwq2 + 3LL * DD * K2Q, DD, DD);           // 2
    {
        dim3 g(GMX, DD / 128, 1);
        mma_gemm<<<g, 256, GSMEM_TOTAL>>>(px2 + 0LL * NN * K2Q, pwq2 + 0LL * DD * K2Q, // 3
                                          bq + 0 * DD, pQ + 0 * sND, nullptr,
                                          NN, K2Q, DD, 0, 0, 0, 0, 0);
        mma_gemm<<<g, 256, GSMEM_TOTAL>>>(px2 + 3LL * NN * K2Q, pwq2 + 3LL * DD * K2Q,
                                          bq + 3 * DD, pQ + 3 * sND, nullptr,
                                          NN, K2Q, DD, 0, 0, 0, 0, 0);
    }

    // weight folds
    for (int r = 0; r < RR; r++) {
        combine_w_kernel<<<CW, 256>>>(Wk, W_attn, pWkr + (long long)r * sDD, stype[r], r);
        combine_w_kernel<<<CW, 256>>>(Wv, W_msg, pWvr + (long long)r * sDD, stype[r], r);
    }
    combine_b_kernel<<<1, DD>>>(bk, W_attn, pbkv1 + 0,   stype[0], 0);
    combine_b_kernel<<<1, DD>>>(bv, W_msg,  pbkv1 + 256, stype[0], 0);
    combine_b_kernel<<<1, DD>>>(bk, W_attn, pbkv1 + 512, stype[3], 3);
    combine_b_kernel<<<1, DD>>>(bv, W_msg,  pbkv1 + 768, stype[3], 3);
    combine_b_kernel<<<1, DD>>>(bk, W_attn, pbkv2 + 0,   stype[1], 1);
    combine_b_kernel<<<1, DD>>>(bv, W_msg,  pbkv2 + 256, stype[1], 1);
    combine_b_kernel<<<1, DD>>>(bk, W_attn, pbkv3 + 0,   stype[2], 2);
    combine_b_kernel<<<1, DD>>>(bv, W_msg,  pbkv3 + 256, stype[2], 2);
    // paired fp16 weights into concatenated buffers
    pair_w_kernel<<<CW, 256>>>(pWkr + 0LL * sDD, pwkv1 + 0LL   * K2Q, DD, DD);  // r0 k
    pair_w_kernel<<<CW, 256>>>(pWvr + 0LL * sDD, pwkv1 + 256LL * K2Q, DD, DD);  // r0 v
    pair_w_kernel<<<CW, 256>>>(pWkr + 3LL * sDD, pwkv1 + 512LL * K2Q, DD, DD);  // r3 k
    pair_w_kernel<<<CW, 256>>>(pWvr + 3LL * sDD, pwkv1 + 768LL * K2Q, DD, DD);  // r3 v
    pair_w_kernel<<<CW, 256>>>(pWkr + 1LL * sDD, pwkv2 + 0LL   * K2Q, DD, DD);  // r1 k
    pair_w_kernel<<<CW, 256>>>(pWvr + 1LL * sDD, pwkv2 + 256LL * K2Q, DD, DD);  // r1 v
    pair_w_kernel<<<CW, 256>>>(pWkr + 2LL * sDD, pwkv3 + 0LL   * K2Q, DD, DD);  // r2 k
    pair_w_kernel<<<CW, 256>>>(pWvr + 2LL * sDD, pwkv3 + 256LL * K2Q, DD, DD);  // r2 v
    for (int t = 0; t < TT; t++) {
        pair_w_kernel<<<(DD * D4 + 255) / 256, 256>>>(ffn_w1 + (long long)t * DD * D4,
                                                      pw12 + (long long)t * D4 * K2Q, DD, D4);
        pair_w_kernel<<<(D4 * DD + 255) / 256, 256>>>(ffn_w2 + (long long)t * D4 * DD,
                                                      pw22 + (long long)t * DD * K2F, D4, DD);
    }

    // batched K/V GEMMs per source type
    {
        dim3 g1(GMX, 1024 / 128, 1);
        mma_gemm<<<g1, 256, GSMEM_TOTAL>>>(px2 + 1LL * NN * K2Q, pwkv1, pbkv1, pkv1, nullptr,
                                           NN, K2Q, 1024, 0, 0, 0, 0, 0);
        dim3 g2(GMX, 512 / 128, 1);
        mma_gemm<<<g2, 256, GSMEM_TOTAL>>>(px2 + 2LL * NN * K2Q, pwkv2, pbkv2, pkv2, nullptr,
                                           NN, K2Q, 512, 0, 0, 0, 0, 0);
        mma_gemm<<<g2, 256, GSMEM_TOTAL>>>(px2 + 3LL * NN * K2Q, pwkv3, pbkv3, pkv3, nullptr,
                                           NN, K2Q, 512, 0, 0, 0, 0, 0);
    }

    // edge phase (all relations in one pass)
    cudaMemsetAsync(pagg, 0, sizeof(float) * TT * NN * DD, 0);
    cudaMemsetAsync(pm, 0, sizeof(unsigned) * RR * NN * HH, 0);
    cudaMemsetAsync(pz, 0, sizeof(float) * RR * NN * HH, 0);
    {
        long long ne = (long long)RR * EE;
        edge_dot_all<<<(unsigned)((ne + 7) / 8), 256>>>(pQ, pkv1, pkv2, pkv3, esrc, edst, relbias);
        long long nh = ne * HH;
        seg_exp_all<<<(unsigned)((nh + 255) / 256), 256>>>(edst);
        recip_z_kernel<<<(RR * NN * HH + 255) / 256, 256>>>();
        long long nm = ne * 64;
        seg_msg_all<<<(unsigned)((nm + 255) / 256), 256>>>(esrc, edst, pkv1, pkv2, pkv3, pagg);
    }

    // h = LN1(x + agg) (+ fp16 pair h2)
    ln_kernel<<<(TT * NN + 7) / 8, 256>>>(x, pagg, ln1_g, ln1_b, ph, ph2);

    // FFN1: fh = pair(gelu(h @ W1 + b1))
    {
        dim3 g(GMX, D4 / 128, TT);
        mma_gemm<<<g, 256, GSMEM_TOTAL>>>(ph2, pw12, ffn_b1, nullptr, pfh,
                                          NN, K2Q, D4,
                                          (long long)NN * K2Q, (long long)D4 * K2Q,
                                          D4, (long long)NN * D4, 1);
    }
    // FFN2: f2 = fh @ W2 + b2
    {
        dim3 g(GMX, DD / 128, TT);
        mma_gemm<<<g, 256, GSMEM_TOTAL>>>(pfh, pw22, ffn_b2, pf2, nullptr,
                                          NN, K2F, DD,
                                          (long long)NN * K2F, (long long)DD * K2F,
                                          DD, sND, 0);
    }

    // out = LN2(h + f2)
    ln_kernel<<<(TT * NN + 7) / 8, 256>>>(ph, pf2, ln2_g, ln2_b, out, nullptr);

    (void)in_sizes; (void)n_in; (void)out_size;
}

// round 11
// speedup vs baseline: 1.4731x; 1.4731x over previous
#include <cuda_runtime.h>
#include <cuda_fp16.h>
#include <math.h>
#include <stdint.h>

#define TT 4
#define NN 50000
#define DD 256
#define HH 8
#define RR 4
#define EE 200000
#define DK 32
#define D4 1024

// ---------------- scratch (device globals; allocation is forbidden) ----------------
__device__ __align__(16) float    g_Q[(size_t)TT*NN*DD];
__device__ __align__(16) float    g_kv1[(size_t)NN*1024];   // st=1: [k_r0|v_r0|k_r3|v_r3]
__device__ __align__(16) float    g_kv2[(size_t)NN*512];    // st=2: [k_r1|v_r1]
__device__ __align__(16) float    g_kv3[(size_t)NN*512];    // st=3: [k_r2|v_r2]
__device__ __align__(16) float    g_agg[(size_t)TT*NN*DD];
__device__ __align__(16) float    g_h[(size_t)TT*NN*DD];
__device__ __align__(16) float    g_f2[(size_t)TT*NN*DD];
__device__ __align__(16) float    g_logits[(size_t)RR*EE*HH];
__device__ __align__(16) float    g_p[(size_t)RR*EE*HH];
__device__ __align__(16) unsigned g_m[(size_t)RR*NN*HH];
__device__ __align__(16) float    g_z[(size_t)RR*NN*HH];
__device__ __align__(16) float    g_Wkr[RR*DD*DD];
__device__ __align__(16) float    g_Wvr[RR*DD*DD];
__device__ __align__(16) float    g_bkv1[1024];
__device__ __align__(16) float    g_bkv2[512];
__device__ __align__(16) float    g_bkv3[512];
// pure-fp16 operands (hi only)
__device__ __align__(256) __half g_x2[(size_t)TT*NN*DD];
__device__ __align__(256) __half g_h2[(size_t)TT*NN*DD];
__device__ __align__(256) __half g_fh[(size_t)TT*NN*D4];
__device__ __align__(256) __half g_wq2[(size_t)TT*DD*DD];
__device__ __align__(256) __half g_wkv1[(size_t)1024*DD];
__device__ __align__(256) __half g_wkv2[(size_t)512*DD];
__device__ __align__(256) __half g_wkv3[(size_t)512*DD];
__device__ __align__(256) __half g_w12[(size_t)TT*D4*DD];
__device__ __align__(256) __half g_w22[(size_t)TT*DD*D4];

// ---------------- small helpers ----------------
__device__ __forceinline__ unsigned fenc(float f) {
    unsigned u = __float_as_uint(f);
    return (u & 0x80000000u) ? ~u : (u | 0x80000000u);
}
__device__ __forceinline__ float fdec(unsigned u) {
    unsigned b = (u & 0x80000000u) ? (u & 0x7FFFFFFFu) : ~u;
    return __uint_as_float(b);
}
__device__ __forceinline__ uint32_t smem_u32(const void* p) {
    return (uint32_t)__cvta_generic_to_shared(p);
}
__device__ __forceinline__ void cp16(uint32_t d, const void* g, int sz) {
    asm volatile("cp.async.cg.shared.global [%0], [%1], 16, %2;"
                 :: "r"(d), "l"(g), "r"(sz));
}
__device__ __forceinline__ void cp_commit() {
    asm volatile("cp.async.commit_group;");
}
__device__ __forceinline__ void ldm_x4(uint32_t* r, uint32_t a) {
    asm volatile("ldmatrix.sync.aligned.m8n8.x4.shared.b16 {%0,%1,%2,%3}, [%4];"
                 : "=r"(r[0]), "=r"(r[1]), "=r"(r[2]), "=r"(r[3]) : "r"(a));
}
__device__ __forceinline__ void mma16816(float* c, const uint32_t* a,
                                         uint32_t b0, uint32_t b1) {
    asm volatile(
        "mma.sync.aligned.m16n8k16.row.col.f32.f16.f16.f32 "
        "{%0,%1,%2,%3}, {%4,%5,%6,%7}, {%8,%9}, {%0,%1,%2,%3};"
        : "+f"(c[0]), "+f"(c[1]), "+f"(c[2]), "+f"(c[3])
        : "r"(a[0]), "r"(a[1]), "r"(a[2]), "r"(a[3]), "r"(b0), "r"(b1));
}

// ---------------- mma.sync fp16 GEMM (hoisted addressing) ----------------
#define ROWB 80
#define STAGE_B (128*ROWB*2)
#define GSMEM_TOTAL (4*STAGE_B)

__global__ void __launch_bounds__(256, 2)
mma_gemm(const __half* __restrict__ A2, const __half* __restrict__ B2,
         const float* __restrict__ bias, float* __restrict__ Cout,
         __half* __restrict__ C2out,
         int M, int K2, int Nout,
         long long sA, long long sB, long long sBias, long long sC, int epi)
{
    extern __shared__ __align__(128) char smem[];
    const int t = blockIdx.z;
    A2 += (long long)t * sA;
    B2 += (long long)t * sB;
    bias += (long long)t * sBias;
    if (Cout)  Cout  += (long long)t * sC;
    if (C2out) C2out += (long long)t * sC;

    const uint32_t sb = smem_u32(smem);
    const int tid = threadIdx.x;
    const int wid = tid >> 5;
    const int lane = tid & 31;
    const int wm = wid >> 2;
    const int wn = wid & 3;

    const int bm = blockIdx.x * 128;
    const int bn = blockIdx.y * 128;
    const int NC = K2 >> 5;

    // ---- hoisted cp.async addressing (each thread moves 2 A rows + 2 B rows) ----
    const int crow = tid >> 2;          // 0..63
    const int cc4  = tid & 3;           // 0..3 (16B segment)
    const __half* srcA0 = A2 + (long long)(bm + crow) * K2 + cc4 * 8;
    const __half* srcA1 = srcA0 + (long long)64 * K2;
    const __half* srcB0 = B2 + (long long)(bn + crow) * K2 + cc4 * 8;
    const __half* srcB1 = srcB0 + (long long)64 * K2;
    const int szA0 = (bm + crow      < M) ? 16 : 0;
    const int szA1 = (bm + crow + 64 < M) ? 16 : 0;
    const uint32_t dA0 = sb + crow * ROWB + cc4 * 16;
    const uint32_t dA1 = dA0 + 64 * ROWB;
    const uint32_t dB0 = dA0 + 128 * ROWB;
    const uint32_t dB1 = dB0 + 64 * ROWB;

    // ---- hoisted ldmatrix addressing (slot 0; add rolling offset in loop) ----
    uint32_t a_ld[2][4], b_ld[2][2];
#pragma unroll
    for (int kh = 0; kh < 2; kh++) {
        int col2 = (kh * 16 + ((lane >> 4) << 3)) * 2;
#pragma unroll
        for (int mi = 0; mi < 4; mi++)
            a_ld[kh][mi] = sb + (wm * 64 + mi * 16 + (lane & 15)) * ROWB + col2;
#pragma unroll
        for (int bi = 0; bi < 2; bi++)
            b_ld[kh][bi] = sb + 128 * ROWB + (wn * 32 + bi * 16 + (lane & 15)) * ROWB + col2;
    }

    float acc[4][4][4];
#pragma unroll
    for (int i = 0; i < 4; i++)
#pragma unroll
        for (int j = 0; j < 4; j++)
#pragma unroll
            for (int c = 0; c < 4; c++) acc[i][j][c] = 0.f;

    uint32_t wo = 0;   // write slot offset
#define LOADN do {                                              \
        cp16(dA0 + wo, srcA0, szA0); cp16(dA1 + wo, srcA1, szA1); \
        cp16(dB0 + wo, srcB0, 16);   cp16(dB1 + wo, srcB1, 16);   \
        cp_commit();                                              \
        srcA0 += 32; srcA1 += 32; srcB0 += 32; srcB1 += 32;       \
        wo += STAGE_B; if (wo == 4 * STAGE_B) wo = 0;             \
    } while (0)

    LOADN; LOADN; LOADN;

    uint32_t ro = 0;   // read slot offset
    for (int j = 0; j < NC; j++) {
        int wg = NC - 1 - j; if (wg > 2) wg = 2;
        if (wg == 2)      asm volatile("cp.async.wait_group 2;");
        else if (wg == 1) asm volatile("cp.async.wait_group 1;");
        else              asm volatile("cp.async.wait_group 0;");
        __syncthreads();
        if (j + 3 < NC) LOADN;

#pragma unroll
        for (int kh = 0; kh < 2; kh++) {
            uint32_t afr[4][4];
#pragma unroll
            for (int mi = 0; mi < 4; mi++) ldm_x4(afr[mi], a_ld[kh][mi] + ro);
            uint32_t bfr[2][4];
#pragma unroll
            for (int bi = 0; bi < 2; bi++) ldm_x4(bfr[bi], b_ld[kh][bi] + ro);
#pragma unroll
            for (int mi = 0; mi < 4; mi++)
#pragma unroll
                for (int ni = 0; ni < 4; ni++) {
                    uint32_t b0 = bfr[ni >> 1][ni & 1];
                    uint32_t b1 = bfr[ni >> 1][(ni & 1) + 2];
                    mma16816(acc[mi][ni], afr[mi], b0, b1);
                }
        }
        ro += STAGE_B; if (ro == 4 * STAGE_B) ro = 0;
    }
#undef LOADN

#pragma unroll
    for (int mi = 0; mi < 4; mi++) {
#pragma unroll
        for (int half = 0; half < 2; half++) {
            int row = bm + wm * 64 + mi * 16 + (lane >> 2) + half * 8;
            if (row >= M) continue;
#pragma unroll
            for (int ni = 0; ni < 4; ni++) {
                int col = bn + wn * 32 + ni * 8 + ((lane & 3) << 1);
                float v0 = acc[mi][ni][half * 2 + 0] + bias[col + 0];
                float v1 = acc[mi][ni][half * 2 + 1] + bias[col + 1];
                if (epi == 0) {
                    float2 v = make_float2(v0, v1);
                    *(float2*)&Cout[(long long)row * Nout + col] = v;
                } else {
                    v0 = 0.5f * v0 * (1.f + erff(v0 * 0.7071067811865476f));
                    v1 = 0.5f * v1 * (1.f + erff(v1 * 0.7071067811865476f));
                    __half2 hp;
                    hp.x = __float2half_rn(v0);
                    hp.y = __float2half_rn(v1);
                    *(__half2*)&C2out[(long long)row * Nout + col] = hp;
                }
            }
        }
    }
}

// ---------------- weight fold (fp32) ----------------
__global__ void __launch_bounds__(256)
combine_w_kernel(const float* __restrict__ W, const float* __restrict__ Wrel,
                 float* __restrict__ outW, int st, int r)
{
    int idx = blockIdx.x * 256 + threadIdx.x;
    if (idx >= DD * DD) return;
    int d = idx >> 8;
    int c = idx & 255;
    int h = c >> 5, f = c & 31;
    const float* wrow = W + ((long long)st * DD + d) * DD + h * DK;
    const float* wr   = Wrel + ((long long)(r * HH + h) * DK) * DK + f;
    float s = 0.f;
#pragma unroll
    for (int k = 0; k < DK; k++) s = fmaf(wrow[k], wr[k * DK], s);
    outW[idx] = s;
}

__global__ void
combine_b_kernel(const float* __restrict__ b, const float* __restrict__ Wrel,
                 float* __restrict__ outb, int st, int r)
{
    int c = blockIdx.x * blockDim.x + threadIdx.x;
    if (c >= DD) return;
    int h = c >> 5, f = c & 31;
    const float* br = b + st * DD + h * DK;
    const float* wr = Wrel + ((long long)(r * HH + h) * DK) * DK + f;
    float s = 0.f;
#pragma unroll
    for (int k = 0; k < DK; k++) s = fmaf(br[k], wr[k * DK], s);
    outb[c] = s;
}

// ---------------- fp16 conversions ----------------
// elementwise hi conversion (same layout)
__global__ void __launch_bounds__(256)
half_a_kernel(const float* __restrict__ A, __half* __restrict__ A2, long long total)
{
    long long i = (long long)blockIdx.x * 256 + threadIdx.x;
    if (i >= total) return;
    A2[i] = __float2half_rn(A[i]);
}

// W[K][Nw] -> W2[Nw][K] (transpose)
__global__ void __launch_bounds__(256)
half_w_kernel(const float* __restrict__ W, __half* __restrict__ W2,
              int K, int Nw)
{
    int i = blockIdx.x * 256 + threadIdx.x;
    if (i >= K * Nw) return;
    int k = i / Nw, n = i - k * Nw;
    W2[(long long)n * K + k] = __float2half_rn(W[i]);
}

// ---------------- merged edge phase across all relations ----------------
__device__ __constant__ int c_dt[RR]    = {0, 0, 3, 3};
__device__ __constant__ int c_pitch[RR] = {1024, 512, 512, 1024};
__device__ __constant__ int c_koff[RR]  = {0, 0, 0, 512};
__device__ __constant__ int c_voff[RR]  = {256, 256, 256, 768};

__device__ __forceinline__ const float* kv_base(int r, const float* kv1,
                                                const float* kv2, const float* kv3) {
    return (r == 1) ? kv2 : (r == 2) ? kv3 : kv1;
}

__global__ void __launch_bounds__(256)
edge_dot_all(const float* __restrict__ Q, const float* __restrict__ kv1,
             const float* __restrict__ kv2, const float* __restrict__ kv3,
             const int* __restrict__ esrc, const int* __restrict__ edst,
             const float* __restrict__ rel_bias)
{
    const int warp = threadIdx.x >> 5;
    const int lane = threadIdx.x & 31;
    const int h = lane >> 2, q = lane & 3;
    long long ge = (long long)blockIdx.x * 8 + warp;
    if (ge >= (long long)RR * EE) return;
    int r = (int)(ge / EE);
    int s = esrc[ge];
    int d = edst[ge];
    const float* kb = kv_base(r, kv1, kv2, kv3);
    const float4* qp = (const float4*)&Q[((long long)c_dt[r] * NN + d) * DD + h * DK + q * 8];
    const float4* kp = (const float4*)&kb[(long long)s * c_pitch[r] + c_koff[r] + h * DK + q * 8];
    float4 q0 = qp[0], q1 = qp[1];
    float4 k0 = kp[0], k1 = kp[1];
    float acc = q0.x * k0.x + q0.y * k0.y + q0.z * k0.z + q0.w * k0.w
              + q1.x * k1.x + q1.y * k1.y + q1.z * k1.z + q1.w * k1.w;
    acc += __shfl_xor_sync(0xffffffffu, acc, 1);
    acc += __shfl_xor_sync(0xffffffffu, acc, 2);
    if (q == 0) {
        float lg = acc * 0.17677669529663687f + rel_bias[r];
        g_logits[ge * HH + h] = lg;
        atomicMax(&g_m[((long long)r * NN + d) * HH + h], fenc(lg));
    }
}

__global__ void __launch_bounds__(256)
seg_exp_all(const int* __restrict__ edst)
{
    long long i = (long long)blockIdx.x * 256 + threadIdx.x;
    if (i >= (long long)RR * EE * HH) return;
    long long ge = i >> 3;
    int h = (int)(i & 7);
    int r = (int)(ge / EE);
    int d = edst[ge];
    long long mz = ((long long)r * NN + d) * HH + h;
    float m = fdec(g_m[mz]);
    float p = expf(g_logits[i] - m);
    g_p[i] = p;
    atomicAdd(&g_z[mz], p);
}

// z -> 1/z (entries for nodes with no edges stay unused)
__global__ void __launch_bounds__(256)
recip_z_kernel()
{
    int i = blockIdx.x * 256 + threadIdx.x;
    if (i >= RR * NN * HH) return;
    float z = g_z[i];
    g_z[i] = (z != 0.f) ? (1.f / z) : 0.f;
}

__global__ void __launch_bounds__(256)
seg_msg_all(const int* __restrict__ esrc, const int* __restrict__ edst,
            const float* __restrict__ kv1, const float* __restrict__ kv2,
            const float* __restrict__ kv3, float* __restrict__ agg)
{
    long long i = (long long)blockIdx.x * 256 + threadIdx.x;   // RR*EE*64
    if (i >= (long long)RR * EE * 64) return;
    long long ge = i >> 6;
    int c = (int)(i & 63) * 4;
    int h = c >> 5;
    int r = (int)(ge / EE);
    int s = esrc[ge];
    int d = edst[ge];
    // g_z holds reciprocal -> multiply, no division
    float attn = g_p[ge * HH + h] * g_z[((long long)r * NN + d) * HH + h];
    const float* vb = kv_base(r, kv1, kv2, kv3);
    float4 v = *(const float4*)&vb[(long long)s * c_pitch[r] + c_voff[r] + c];
    float* dst = &agg[((long long)c_dt[r] * NN + d) * DD + c];
    asm volatile("red.global.add.v4.f32 [%0], {%1,%2,%3,%4};"
                 :: "l"(dst), "f"(attn * v.x), "f"(attn * v.y),
                    "f"(attn * v.z), "f"(attn * v.w)
                 : "memory");
}

// ---------------- layernorm(residual) [+ optional fp16 out] ----------------
__global__ void __launch_bounds__(256)
ln_kernel(const float* __restrict__ X, const float* __restrict__ Res,
          const float* __restrict__ G, const float* __restrict__ B,
          float* __restrict__ Out, __half* __restrict__ Out2)
{
    int row = blockIdx.x * 8 + (threadIdx.x >> 5);
    if (row >= TT * NN) return;
    int lane = threadIdx.x & 31;
    int t = row / NN;
    const float* xr = X + (long long)row * DD;
    const float* rr = Res + (long long)row * DD;
    float v[8];
    float sum = 0.f;
#pragma unroll
    for (int j = 0; j < 8; j++) {
        v[j] = xr[lane + 32 * j] + rr[lane + 32 * j];
        sum += v[j];
    }
#pragma unroll
    for (int o = 16; o > 0; o >>= 1) sum += __shfl_xor_sync(0xffffffffu, sum, o);
    float mu = sum * (1.f / 256.f);
    float var = 0.f;
#pragma unroll
    for (int j = 0; j < 8; j++) {
        float dlt = v[j] - mu;
        var = fmaf(dlt, dlt, var);
    }
#pragma unroll
    for (int o = 16; o > 0; o >>= 1) var += __shfl_xor_sync(0xffffffffu, var, o);
    float rstd = rsqrtf(var * (1.f / 256.f) + 1e-5f);
#pragma unroll
    for (int j = 0; j < 8; j++) {
        int c = lane + 32 * j;
        float y = (v[j] - mu) * rstd * G[t * DD + c] + B[t * DD + c];
        Out[(long long)row * DD + c] = y;
        if (Out2) Out2[(long long)row * DD + c] = __float2half_rn(y);
    }
}

// ---------------- launch ----------------
extern "C" void kernel_launch(void* const* d_in, const int* in_sizes, int n_in,
                              void* d_out, int out_size)
{
    const float* x       = (const float*)d_in[0];
    const int*   esrc    = (const int*)d_in[1];
    const int*   edst    = (const int*)d_in[2];
    const float* Wq      = (const float*)d_in[3];
    const float* bq      = (const float*)d_in[4];
    const float* Wk      = (const float*)d_in[5];
    const float* bk      = (const float*)d_in[6];
    const float* Wv      = (const float*)d_in[7];
    const float* bv      = (const float*)d_in[8];
    const float* W_attn  = (const float*)d_in[9];
    const float* W_msg   = (const float*)d_in[10];
    const float* relbias = (const float*)d_in[11];
    const float* ln1_g   = (const float*)d_in[12];
    const float* ln1_b   = (const float*)d_in[13];
    const float* ln2_g   = (const float*)d_in[14];
    const float* ln2_b   = (const float*)d_in[15];
    const float* ffn_w1  = (const float*)d_in[16];
    const float* ffn_b1  = (const float*)d_in[17];
    const float* ffn_w2  = (const float*)d_in[18];
    const float* ffn_b2  = (const float*)d_in[19];
    float* out = (float*)d_out;

    float *pQ, *pkv1, *pkv2, *pkv3, *pagg, *ph, *pf2, *pz;
    float *pWkr, *pWvr, *pbkv1, *pbkv2, *pbkv3;
    unsigned* pm;
    __half *px2, *ph2, *pfh, *pwq2, *pwkv1, *pwkv2, *pwkv3, *pw12, *pw22;
    cudaGetSymbolAddress((void**)&pQ, g_Q);
    cudaGetSymbolAddress((void**)&pkv1, g_kv1);
    cudaGetSymbolAddress((void**)&pkv2, g_kv2);
    cudaGetSymbolAddress((void**)&pkv3, g_kv3);
    cudaGetSymbolAddress((void**)&pagg, g_agg);
    cudaGetSymbolAddress((void**)&ph, g_h);
    cudaGetSymbolAddress((void**)&pf2, g_f2);
    cudaGetSymbolAddress((void**)&pm, g_m);
    cudaGetSymbolAddress((void**)&pz, g_z);
    cudaGetSymbolAddress((void**)&pWkr, g_Wkr);
    cudaGetSymbolAddress((void**)&pWvr, g_Wvr);
    cudaGetSymbolAddress((void**)&pbkv1, g_bkv1);
    cudaGetSymbolAddress((void**)&pbkv2, g_bkv2);
    cudaGetSymbolAddress((void**)&pbkv3, g_bkv3);
    cudaGetSymbolAddress((void**)&px2, g_x2);
    cudaGetSymbolAddress((void**)&ph2, g_h2);
    cudaGetSymbolAddress((void**)&pfh, g_fh);
    cudaGetSymbolAddress((void**)&pwq2, g_wq2);
    cudaGetSymbolAddress((void**)&pwkv1, g_wkv1);
    cudaGetSymbolAddress((void**)&pwkv2, g_wkv2);
    cudaGetSymbolAddress((void**)&pwkv3, g_wkv3);
    cudaGetSymbolAddress((void**)&pw12, g_w12);
    cudaGetSymbolAddress((void**)&pw22, g_w22);

    cudaFuncSetAttribute(mma_gemm, cudaFuncAttributeMaxDynamicSharedMemorySize, GSMEM_TOTAL);

    const long long sND = (long long)NN * DD;
    const long long sDD = (long long)DD * DD;
    const int stype[RR] = {1, 2, 3, 1};
    const int GMX = (NN + 127) / 128;   // 391
    const int CW = (DD * DD + 255) / 256;

    // launches 0-2: prereqs; launch index 3 = representative GEMM (profiled)
    {
        long long total = (long long)TT * NN * DD;
        half_a_kernel<<<(unsigned)((total + 255) / 256), 256>>>(x, px2, total);        // 0
    }
    half_w_kernel<<<CW, 256>>>(Wq + 0 * sDD, pwq2 + 0LL * sDD, DD, DD);                // 1
    half_w_kernel<<<CW, 256>>>(Wq + 3 * sDD, pwq2 + 3LL * sDD, DD, DD);                // 2
    {
        dim3 g(GMX, DD / 128, 1);
        mma_gemm<<<g, 256, GSMEM_TOTAL>>>(px2 + 0LL * sND, pwq2 + 0LL * sDD,           // 3
                                          bq + 0 * DD, pQ + 0 * sND, nullptr,
                                          NN, DD, DD, 0, 0, 0, 0, 0);
        mma_gemm<<<g, 256, GSMEM_TOTAL>>>(px2 + 3LL * sND, pwq2 + 3LL * sDD,
                                          bq + 3 * DD, pQ + 3 * sND, nullptr,
                                          NN, DD, DD, 0, 0, 0, 0, 0);
    }

    // weight folds
    for (int r = 0; r < RR; r++) {
        combine_w_kernel<<<CW, 256>>>(Wk, W_attn, pWkr + (long long)r * sDD, stype[r], r);
        combine_w_kernel<<<CW, 256>>>(Wv, W_msg, pWvr + (long long)r * sDD, stype[r], r);
    }
    combine_b_kernel<<<1, DD>>>(bk, W_attn, pbkv1 + 0,   stype[0], 0);
    combine_b_kernel<<<1, DD>>>(bv, W_msg,  pbkv1 + 256, stype[0], 0);
    combine_b_kernel<<<1, DD>>>(bk, W_attn, pbkv1 + 512, stype[3], 3);
    combine_b_kernel<<<1, DD>>>(bv, W_msg,  pbkv1 + 768, stype[3], 3);
    combine_b_kernel<<<1, DD>>>(bk, W_attn, pbkv2 + 0,   stype[1], 1);
    combine_b_kernel<<<1, DD>>>(bv, W_msg,  pbkv2 + 256, stype[1], 1);
    combine_b_kernel<<<1, DD>>>(bk, W_attn, pbkv3 + 0,   stype[2], 2);
    combine_b_kernel<<<1, DD>>>(bv, W_msg,  pbkv3 + 256, stype[2], 2);
    // fp16 weights into concatenated buffers (W2 row = output channel, K contiguous)
    half_w_kernel<<<CW, 256>>>(pWkr + 0LL * sDD, pwkv1 + 0LL   * DD, DD, DD);  // r0 k
    half_w_kernel<<<CW, 256>>>(pWvr + 0LL * sDD, pwkv1 + 256LL * DD, DD, DD);  // r0 v
    half_w_kernel<<<CW, 256>>>(pWkr + 3LL * sDD, pwkv1 + 512LL * DD, DD, DD);  // r3 k
    half_w_kernel<<<CW, 256>>>(pWvr + 3LL * sDD, pwkv1 + 768LL * DD, DD, DD);  // r3 v
    half_w_kernel<<<CW, 256>>>(pWkr + 1LL * sDD, pwkv2 + 0LL   * DD, DD, DD);  // r1 k
    half_w_kernel<<<CW, 256>>>(pWvr + 1LL * sDD, pwkv2 + 256LL * DD, DD, DD);  // r1 v
    half_w_kernel<<<CW, 256>>>(pWkr + 2LL * sDD, pwkv3 + 0LL   * DD, DD, DD);  // r2 k
    half_w_kernel<<<CW, 256>>>(pWvr + 2LL * sDD, pwkv3 + 256LL * DD, DD, DD);  // r2 v
    for (int t = 0; t < TT; t++) {
        half_w_kernel<<<(DD * D4 + 255) / 256, 256>>>(ffn_w1 + (long long)t * DD * D4,
                                                      pw12 + (long long)t * D4 * DD, DD, D4);
        half_w_kernel<<<(D4 * DD + 255) / 256, 256>>>(ffn_w2 + (long long)t * D4 * DD,
                                                      pw22 + (long long)t * DD * D4, D4, DD);
    }

    // batched K/V GEMMs per source type
    {
        dim3 g1(GMX, 1024 / 128, 1);
        mma_gemm<<<g1, 256, GSMEM_TOTAL>>>(px2 + 1LL * sND, pwkv1, pbkv1, pkv1, nullptr,
                                           NN, DD, 1024, 0, 0, 0, 0, 0);
        dim3 g2(GMX, 512 / 128, 1);
        mma_gemm<<<g2, 256, GSMEM_TOTAL>>>(px2 + 2LL * sND, pwkv2, pbkv2, pkv2, nullptr,
                                           NN, DD, 512, 0, 0, 0, 0, 0);
        mma_gemm<<<g2, 256, GSMEM_TOTAL>>>(px2 + 3LL * sND, pwkv3, pbkv3, pkv3, nullptr,
                                           NN, DD, 512, 0, 0, 0, 0, 0);
    }

    // edge phase (all relations in one pass)
    cudaMemsetAsync(pagg, 0, sizeof(float) * TT * NN * DD, 0);
    cudaMemsetAsync(pm, 0, sizeof(unsigned) * RR * NN * HH, 0);
    cudaMemsetAsync(pz, 0, sizeof(float) * RR * NN * HH, 0);
    {
        long long ne = (long long)RR * EE;
        edge_dot_all<<<(unsigned)((ne + 7) / 8), 256>>>(pQ, pkv1, pkv2, pkv3, esrc, edst, relbias);
        long long nh = ne * HH;
        seg_exp_all<<<(unsigned)((nh + 255) / 256), 256>>>(edst);
        recip_z_kernel<<<(RR * NN * HH + 255) / 256, 256>>>();
        long long nm = ne * 64;
        seg_msg_all<<<(unsigned)((nm + 255) / 256), 256>>>(esrc, edst, pkv1, pkv2, pkv3, pagg);
    }

    // h = LN1(x + agg) (+ fp16 h2)
    ln_kernel<<<(TT * NN + 7) / 8, 256>>>(x, pagg, ln1_g, ln1_b, ph, ph2);

    // FFN1: fh = fp16(gelu(h @ W1 + b1))
    {
        dim3 g(GMX, D4 / 128, TT);
        mma_gemm<<<g, 256, GSMEM_TOTAL>>>(ph2, pw12, ffn_b1, nullptr, pfh,
                                          NN, DD, D4,
                                          sND, (long long)D4 * DD,
                                          D4, (long long)NN * D4, 1);
    }
    // FFN2: f2 = fh @ W2 + b2
    {
        dim3 g(GMX, DD / 128, TT);
        mma_gemm<<<g, 256, GSMEM_TOTAL>>>(pfh, pw22, ffn_b2, pf2, nullptr,
                                          NN, D4, DD,
                                          (long long)NN * D4, (long long)DD * D4,
                                          DD, sND, 0);
    }

    // out = LN2(h + f2)
    ln_kernel<<<(TT * NN + 7) / 8, 256>>>(ph, pf2, ln2_g, ln2_b, out, nullptr);

    (void)in_sizes; (void)n_in; (void)out_size;
}

// round 16
// speedup vs baseline: 1.5151x; 1.0285x over previous
#include <cuda_runtime.h>
#include <cuda_fp16.h>
#include <math.h>
#include <stdint.h>

#define TT 4
#define NN 50000
#define DD 256
#define HH 8
#define RR 4
#define EE 200000
#define DK 32
#define D4 1024

// ---------------- scratch (device globals; allocation is forbidden) ----------------
__device__ __align__(16) float    g_Q[(size_t)TT*NN*DD];
__device__ __align__(16) float    g_kv1[(size_t)NN*1024];   // st=1: [k_r0|v_r0|k_r3|v_r3]
__device__ __align__(16) float    g_kv2[(size_t)NN*512];    // st=2: [k_r1|v_r1]
__device__ __align__(16) float    g_kv3[(size_t)NN*512];    // st=3: [k_r2|v_r2]
__device__ __align__(16) float    g_agg[(size_t)TT*NN*DD];
__device__ __align__(16) float    g_h[(size_t)TT*NN*DD];
__device__ __align__(16) float    g_f2[(size_t)TT*NN*DD];
__device__ __align__(16) float    g_logits[(size_t)RR*EE*HH];
__device__ __align__(16) float    g_p[(size_t)RR*EE*HH];
__device__ __align__(16) unsigned g_m[(size_t)RR*NN*HH];
__device__ __align__(16) float    g_z[(size_t)RR*NN*HH];
__device__ __align__(16) float    g_Wkr[RR*DD*DD];
__device__ __align__(16) float    g_Wvr[RR*DD*DD];
__device__ __align__(16) float    g_bkv1[1024];
__device__ __align__(16) float    g_bkv2[512];
__device__ __align__(16) float    g_bkv3[512];
// pure-fp16 operands
__device__ __align__(256) __half g_x2[(size_t)TT*NN*DD];
__device__ __align__(256) __half g_h2[(size_t)TT*NN*DD];
__device__ __align__(256) __half g_fh[(size_t)TT*NN*D4];
__device__ __align__(256) __half g_wq2[(size_t)TT*DD*DD];
__device__ __align__(256) __half g_wkv1[(size_t)1024*DD];
__device__ __align__(256) __half g_wkv2[(size_t)512*DD];
__device__ __align__(256) __half g_wkv3[(size_t)512*DD];
__device__ __align__(256) __half g_w12[(size_t)TT*D4*DD];
__device__ __align__(256) __half g_w22[(size_t)TT*DD*D4];

// ---------------- small helpers ----------------
__device__ __forceinline__ unsigned fenc(float f) {
    unsigned u = __float_as_uint(f);
    return (u & 0x80000000u) ? ~u : (u | 0x80000000u);
}
__device__ __forceinline__ float fdec(unsigned u) {
    unsigned b = (u & 0x80000000u) ? (u & 0x7FFFFFFFu) : ~u;
    return __uint_as_float(b);
}
__device__ __forceinline__ uint32_t smem_u32(const void* p) {
    return (uint32_t)__cvta_generic_to_shared(p);
}
__device__ __forceinline__ void cp16(uint32_t d, const void* g, int sz) {
    asm volatile("cp.async.cg.shared.global [%0], [%1], 16, %2;"
                 :: "r"(d), "l"(g), "r"(sz));
}
__device__ __forceinline__ void cp_commit() {
    asm volatile("cp.async.commit_group;");
}
__device__ __forceinline__ void ldm_x4(uint32_t* r, uint32_t a) {
    asm volatile("ldmatrix.sync.aligned.m8n8.x4.shared.b16 {%0,%1,%2,%3}, [%4];"
                 : "=r"(r[0]), "=r"(r[1]), "=r"(r[2]), "=r"(r[3]) : "r"(a));
}
__device__ __forceinline__ void mma16816(float* c, const uint32_t* a,
                                         uint32_t b0, uint32_t b1) {
    asm volatile(
        "mma.sync.aligned.m16n8k16.row.col.f32.f16.f16.f32 "
        "{%0,%1,%2,%3}, {%4,%5,%6,%7}, {%8,%9}, {%0,%1,%2,%3};"
        : "+f"(c[0]), "+f"(c[1]), "+f"(c[2]), "+f"(c[3])
        : "r"(a[0]), "r"(a[1]), "r"(a[2]), "r"(a[3]), "r"(b0), "r"(b1));
}

// ---------------- fp16 GEMM core (software-pipelined fragments) ----------------
#define ROWB 80
#define STAGE_B (128*ROWB*2)
#define GSMEM_TOTAL (4*STAGE_B)

__device__ __forceinline__ void gemm_core(
    const __half* __restrict__ A2, const __half* __restrict__ B2,
    const float* __restrict__ bias, float* __restrict__ Cout,
    __half* __restrict__ C2out, int M, int K2, int Nout,
    int bm, int bn, char* smem, int epi)
{
    const uint32_t sb = smem_u32(smem);
    const int tid = threadIdx.x;
    const int wid = tid >> 5;
    const int lane = tid & 31;
    const int wm = wid >> 2;
    const int wn = wid & 3;
    const int NC = K2 >> 5;

    // hoisted cp.async addressing
    const int crow = tid >> 2;
    const int cc4  = tid & 3;
    const __half* srcA0 = A2 + (long long)(bm + crow) * K2 + cc4 * 8;
    const __half* srcA1 = srcA0 + (long long)64 * K2;
    const __half* srcB0 = B2 + (long long)(bn + crow) * K2 + cc4 * 8;
    const __half* srcB1 = srcB0 + (long long)64 * K2;
    const int szA0 = (bm + crow      < M) ? 16 : 0;
    const int szA1 = (bm + crow + 64 < M) ? 16 : 0;
    const uint32_t dA0 = sb + crow * ROWB + cc4 * 16;
    const uint32_t dA1 = dA0 + 64 * ROWB;
    const uint32_t dB0 = dA0 + 128 * ROWB;
    const uint32_t dB1 = dB0 + 64 * ROWB;

    // ldmatrix addresses for kh=0; kh=1 is +32 bytes
    uint32_t a_ld[4], b_ld[2];
    {
        int col2 = ((lane >> 4) << 4);   // (lane>>4)*8 elems *2B
        #pragma unroll
        for (int mi = 0; mi < 4; mi++)
            a_ld[mi] = sb + (wm * 64 + mi * 16 + (lane & 15)) * ROWB + col2;
        #pragma unroll
        for (int bi = 0; bi < 2; bi++)
            b_ld[bi] = sb + 128 * ROWB + (wn * 32 + bi * 16 + (lane & 15)) * ROWB + col2;
    }

    float acc[4][4][4];
#pragma unroll
    for (int i = 0; i < 4; i++)
#pragma unroll
        for (int j = 0; j < 4; j++)
#pragma unroll
            for (int c = 0; c < 4; c++) acc[i][j][c] = 0.f;

    uint32_t wo = 0;
#define LOADN do {                                                \
        cp16(dA0 + wo, srcA0, szA0); cp16(dA1 + wo, srcA1, szA1); \
        cp16(dB0 + wo, srcB0, 16);   cp16(dB1 + wo, srcB1, 16);   \
        cp_commit();                                              \
        srcA0 += 32; srcA1 += 32; srcB0 += 32; srcB1 += 32;       \
        wo += STAGE_B; if (wo == 4 * STAGE_B) wo = 0;             \
    } while (0)

    LOADN; LOADN; LOADN;

    uint32_t ro = 0;
    for (int j = 0; j < NC; j++) {
        int wg = NC - 1 - j; if (wg > 2) wg = 2;
        if (wg == 2)      asm volatile("cp.async.wait_group 2;");
        else if (wg == 1) asm volatile("cp.async.wait_group 1;");
        else              asm volatile("cp.async.wait_group 0;");
        __syncthreads();
        if (j + 3 < NC) LOADN;

        // preload BOTH kh B-fragment sets + kh0 A
        uint32_t bfr[2][2][4];
#pragma unroll
        for (int kh = 0; kh < 2; kh++)
#pragma unroll
            for (int bi = 0; bi < 2; bi++)
                ldm_x4(bfr[kh][bi], b_ld[bi] + ro + kh * 32);
        uint32_t afr[4][4];
#pragma unroll
        for (int mi = 0; mi < 4; mi++) ldm_x4(afr[mi], a_ld[mi] + ro);
        // MMA kh0
#pragma unroll
        for (int mi = 0; mi < 4; mi++)
#pragma unroll
            for (int ni = 0; ni < 4; ni++)
                mma16816(acc[mi][ni], afr[mi],
                         bfr[0][ni >> 1][ni & 1], bfr[0][ni >> 1][(ni & 1) + 2]);
        // A kh1 loads hide under kh0 MMA burst
#pragma unroll
        for (int mi = 0; mi < 4; mi++) ldm_x4(afr[mi], a_ld[mi] + ro + 32);
#pragma unroll
        for (int mi = 0; mi < 4; mi++)
#pragma unroll
            for (int ni = 0; ni < 4; ni++)
                mma16816(acc[mi][ni], afr[mi],
                         bfr[1][ni >> 1][ni & 1], bfr[1][ni >> 1][(ni & 1) + 2]);

        ro += STAGE_B; if (ro == 4 * STAGE_B) ro = 0;
    }
#undef LOADN

#pragma unroll
    for (int mi = 0; mi < 4; mi++) {
#pragma unroll
        for (int half = 0; half < 2; half++) {
            int row = bm + wm * 64 + mi * 16 + (lane >> 2) + half * 8;
            if (row >= M) continue;
#pragma unroll
            for (int ni = 0; ni < 4; ni++) {
                int col = bn + wn * 32 + ni * 8 + ((lane & 3) << 1);
                float v0 = acc[mi][ni][half * 2 + 0] + bias[col + 0];
                float v1 = acc[mi][ni][half * 2 + 1] + bias[col + 1];
                if (epi == 0) {
                    float2 v = make_float2(v0, v1);
                    *(float2*)&Cout[(long long)row * Nout + col] = v;
                } else {
                    v0 = 0.5f * v0 * (1.f + erff(v0 * 0.7071067811865476f));
                    v1 = 0.5f * v1 * (1.f + erff(v1 * 0.7071067811865476f));
                    __half2 hp;
                    hp.x = __float2half_rn(v0);
                    hp.y = __float2half_rn(v1);
                    *(__half2*)&C2out[(long long)row * Nout + col] = hp;
                }
            }
        }
    }
}

// generic strided-batch GEMM (z over batch)
__global__ void __launch_bounds__(256, 2)
mma_gemm(const __half* __restrict__ A2, const __half* __restrict__ B2,
         const float* __restrict__ bias, float* __restrict__ Cout,
         __half* __restrict__ C2out,
         int M, int K2, int Nout,
         long long sA, long long sB, long long sBias, long long sC, int epi)
{
    extern __shared__ __align__(128) char smem[];
    const int t = blockIdx.z;
    gemm_core(A2 + (long long)t * sA, B2 + (long long)t * sB,
              bias + (long long)t * sBias,
              Cout ? Cout + (long long)t * sC : nullptr,
              C2out ? C2out + (long long)t * sC : nullptr,
              M, K2, Nout, blockIdx.x * 128, blockIdx.y * 128, smem, epi);
}

// fused KV GEMM: 3 segments, K=DD, M=NN, fp32 out
struct KVSegs {
    const __half* A[3];
    const __half* B[3];
    const float*  bias[3];
    float*        C[3];
    int N[3];
    int nshift[3];   // log2(N/128)
    int start[3];    // first block index of segment
};

__global__ void __launch_bounds__(256, 2)
mma_gemm_kv(KVSegs segs)
{
    extern __shared__ __align__(128) char smem[];
    int b = blockIdx.x;
    int s = (b >= segs.start[2]) ? 2 : (b >= segs.start[1]) ? 1 : 0;
    int local = b - segs.start[s];
    int nb_mask = (1 << segs.nshift[s]) - 1;
    int bm = (local >> segs.nshift[s]) * 128;
    int bn = (local & nb_mask) * 128;
    gemm_core(segs.A[s], segs.B[s], segs.bias[s], segs.C[s], nullptr,
              NN, DD, segs.N[s], bm, bn, smem, 0);
}

// ---------------- weight fold (fp32) ----------------
__global__ void __launch_bounds__(256)
combine_w_kernel(const float* __restrict__ W, const float* __restrict__ Wrel,
                 float* __restrict__ outW, int st, int r)
{
    int idx = blockIdx.x * 256 + threadIdx.x;
    if (idx >= DD * DD) return;
    int d = idx >> 8;
    int c = idx & 255;
    int h = c >> 5, f = c & 31;
    const float* wrow = W + ((long long)st * DD + d) * DD + h * DK;
    const float* wr   = Wrel + ((long long)(r * HH + h) * DK) * DK + f;
    float s = 0.f;
#pragma unroll
    for (int k = 0; k < DK; k++) s = fmaf(wrow[k], wr[k * DK], s);
    outW[idx] = s;
}

__global__ void
combine_b_kernel(const float* __restrict__ b, const float* __restrict__ Wrel,
                 float* __restrict__ outb, int st, int r)
{
    int c = blockIdx.x * blockDim.x + threadIdx.x;
    if (c >= DD) return;
    int h = c >> 5, f = c & 31;
    const float* br = b + st * DD + h * DK;
    const float* wr = Wrel + ((long long)(r * HH + h) * DK) * DK + f;
    float s = 0.f;
#pragma unroll
    for (int k = 0; k < DK; k++) s = fmaf(br[k], wr[k * DK], s);
    outb[c] = s;
}

// ---------------- fp16 conversions ----------------
__global__ void __launch_bounds__(256)
half_a_kernel(const float* __restrict__ A, __half* __restrict__ A2, long long total)
{
    long long i = (long long)blockIdx.x * 256 + threadIdx.x;
    if (i >= total) return;
    A2[i] = __float2half_rn(A[i]);
}

// W[K][Nw] -> W2[Nw][K] (transpose)
__global__ void __launch_bounds__(256)
half_w_kernel(const float* __restrict__ W, __half* __restrict__ W2,
              int K, int Nw)
{
    int i = blockIdx.x * 256 + threadIdx.x;
    if (i >= K * Nw) return;
    int k = i / Nw, n = i - k * Nw;
    W2[(long long)n * K + k] = __float2half_rn(W[i]);
}

// ---------------- merged edge phase across all relations ----------------
__device__ __constant__ int c_dt[RR]    = {0, 0, 3, 3};
__device__ __constant__ int c_pitch[RR] = {1024, 512, 512, 1024};
__device__ __constant__ int c_koff[RR]  = {0, 0, 0, 512};
__device__ __constant__ int c_voff[RR]  = {256, 256, 256, 768};

__device__ __forceinline__ const float* kv_base(int r, const float* kv1,
                                                const float* kv2, const float* kv3) {
    return (r == 1) ? kv2 : (r == 2) ? kv3 : kv1;
}

__global__ void __launch_bounds__(256)
edge_dot_all(const float* __restrict__ Q, const float* __restrict__ kv1,
             const float* __restrict__ kv2, const float* __restrict__ kv3,
             const int* __restrict__ esrc, const int* __restrict__ edst,
             const float* __restrict__ rel_bias)
{
    const int warp = threadIdx.x >> 5;
    const int lane = threadIdx.x & 31;
    const int h = lane >> 2, q = lane & 3;
    long long ge = (long long)blockIdx.x * 8 + warp;
    if (ge >= (long long)RR * EE) return;
    int r = (int)(ge / EE);
    int s = esrc[ge];
    int d = edst[ge];
    const float* kb = kv_base(r, kv1, kv2, kv3);
    const float4* qp = (const float4*)&Q[((long long)c_dt[r] * NN + d) * DD + h * DK + q * 8];
    const float4* kp = (const float4*)&kb[(long long)s * c_pitch[r] + c_koff[r] + h * DK + q * 8];
    float4 q0 = qp[0], q1 = qp[1];
    float4 k0 = kp[0], k1 = kp[1];
    float acc = q0.x * k0.x + q0.y * k0.y + q0.z * k0.z + q0.w * k0.w
              + q1.x * k1.x + q1.y * k1.y + q1.z * k1.z + q1.w * k1.w;
    acc += __shfl_xor_sync(0xffffffffu, acc, 1);
    acc += __shfl_xor_sync(0xffffffffu, acc, 2);
    if (q == 0) {
        float lg = acc * 0.17677669529663687f + rel_bias[r];
        g_logits[ge * HH + h] = lg;
        atomicMax(&g_m[((long long)r * NN + d) * HH + h], fenc(lg));
    }
}

__global__ void __launch_bounds__(256)
seg_exp_all(const int* __restrict__ edst)
{
    long long i = (long long)blockIdx.x * 256 + threadIdx.x;
    if (i >= (long long)RR * EE * HH) return;
    long long ge = i >> 3;
    int h = (int)(i & 7);
    int r = (int)(ge / EE);
    int d = edst[ge];
    long long mz = ((long long)r * NN + d) * HH + h;
    float m = fdec(g_m[mz]);
    float p = expf(g_logits[i] - m);
    g_p[i] = p;
    atomicAdd(&g_z[mz], p);
}

__global__ void __launch_bounds__(256)
recip_z_kernel()
{
    int i = blockIdx.x * 256 + threadIdx.x;
    if (i >= RR * NN * HH) return;
    float z = g_z[i];
    g_z[i] = (z != 0.f) ? (1.f / z) : 0.f;
}

__global__ void __launch_bounds__(256)
seg_msg_all(const int* __restrict__ esrc, const int* __restrict__ edst,
            const float* __restrict__ kv1, const float* __restrict__ kv2,
            const float* __restrict__ kv3, float* __restrict__ agg)
{
    long long i = (long long)blockIdx.x * 256 + threadIdx.x;   // RR*EE*64
    if (i >= (long long)RR * EE * 64) return;
    long long ge = i >> 6;
    int c = (int)(i & 63) * 4;
    int h = c >> 5;
    int r = (int)(ge / EE);
    int s = esrc[ge];
    int d = edst[ge];
    float attn = g_p[ge * HH + h] * g_z[((long long)r * NN + d) * HH + h];
    const float* vb = kv_base(r, kv1, kv2, kv3);
    float4 v = *(const float4*)&vb[(long long)s * c_pitch[r] + c_voff[r] + c];
    float* dst = &agg[((long long)c_dt[r] * NN + d) * DD + c];
    asm volatile("red.global.add.v4.f32 [%0], {%1,%2,%3,%4};"
                 :: "l"(dst), "f"(attn * v.x), "f"(attn * v.y),
                    "f"(attn * v.z), "f"(attn * v.w)
                 : "memory");
}

// ---------------- layernorm(residual) [+ optional fp16 out] ----------------
__global__ void __launch_bounds__(256)
ln_kernel(const float* __restrict__ X, const float* __restrict__ Res,
          const float* __restrict__ G, const float* __restrict__ B,
          float* __restrict__ Out, __half* __restrict__ Out2)
{
    int row = blockIdx.x * 8 + (threadIdx.x >> 5);
    if (row >= TT * NN) return;
    int lane = threadIdx.x & 31;
    int t = row / NN;
    const float* xr = X + (long long)row * DD;
    const float* rr = Res + (long long)row * DD;
    float v[8];
    float sum = 0.f;
#pragma unroll
    for (int j = 0; j < 8; j++) {
        v[j] = xr[lane + 32 * j] + rr[lane + 32 * j];
        sum += v[j];
    }
#pragma unroll
    for (int o = 16; o > 0; o >>= 1) sum += __shfl_xor_sync(0xffffffffu, sum, o);
    float mu = sum * (1.f / 256.f);
    float var = 0.f;
#pragma unroll
    for (int j = 0; j < 8; j++) {
        float dlt = v[j] - mu;
        var = fmaf(dlt, dlt, var);
    }
#pragma unroll
    for (int o = 16; o > 0; o >>= 1) var += __shfl_xor_sync(0xffffffffu, var, o);
    float rstd = rsqrtf(var * (1.f / 256.f) + 1e-5f);
#pragma unroll
    for (int j = 0; j < 8; j++) {
        int c = lane + 32 * j;
        float y = (v[j] - mu) * rstd * G[t * DD + c] + B[t * DD + c];
        Out[(long long)row * DD + c] = y;
        if (Out2) Out2[(long long)row * DD + c] = __float2half_rn(y);
    }
}

// ---------------- launch ----------------
extern "C" void kernel_launch(void* const* d_in, const int* in_sizes, int n_in,
                              void* d_out, int out_size)
{
    const float* x       = (const float*)d_in[0];
    const int*   esrc    = (const int*)d_in[1];
    const int*   edst    = (const int*)d_in[2];
    const float* Wq      = (const float*)d_in[3];
    const float* bq      = (const float*)d_in[4];
    const float* Wk      = (const float*)d_in[5];
    const float* bk      = (const float*)d_in[6];
    const float* Wv      = (const float*)d_in[7];
    const float* bv      = (const float*)d_in[8];
    const float* W_attn  = (const float*)d_in[9];
    const float* W_msg   = (const float*)d_in[10];
    const float* relbias = (const float*)d_in[11];
    const float* ln1_g   = (const float*)d_in[12];
    const float* ln1_b   = (const float*)d_in[13];
    const float* ln2_g   = (const float*)d_in[14];
    const float* ln2_b   = (const float*)d_in[15];
    const float* ffn_w1  = (const float*)d_in[16];
    const float* ffn_b1  = (const float*)d_in[17];
    const float* ffn_w2  = (const float*)d_in[18];
    const float* ffn_b2  = (const float*)d_in[19];
    float* out = (float*)d_out;

    float *pQ, *pkv1, *pkv2, *pkv3, *pagg, *ph, *pf2, *pz;
    float *pWkr, *pWvr, *pbkv1, *pbkv2, *pbkv3;
    unsigned* pm;
    __half *px2, *ph2, *pfh, *pwq2, *pwkv1, *pwkv2, *pwkv3, *pw12, *pw22;
    cudaGetSymbolAddress((void**)&pQ, g_Q);
    cudaGetSymbolAddress((void**)&pkv1, g_kv1);
    cudaGetSymbolAddress((void**)&pkv2, g_kv2);
    cudaGetSymbolAddress((void**)&pkv3, g_kv3);
    cudaGetSymbolAddress((void**)&pagg, g_agg);
    cudaGetSymbolAddress((void**)&ph, g_h);
    cudaGetSymbolAddress((void**)&pf2, g_f2);
    cudaGetSymbolAddress((void**)&pm, g_m);
    cudaGetSymbolAddress((void**)&pz, g_z);
    cudaGetSymbolAddress((void**)&pWkr, g_Wkr);
    cudaGetSymbolAddress((void**)&pWvr, g_Wvr);
    cudaGetSymbolAddress((void**)&pbkv1, g_bkv1);
    cudaGetSymbolAddress((void**)&pbkv2, g_bkv2);
    cudaGetSymbolAddress((void**)&pbkv3, g_bkv3);
    cudaGetSymbolAddress((void**)&px2, g_x2);
    cudaGetSymbolAddress((void**)&ph2, g_h2);
    cudaGetSymbolAddress((void**)&pfh, g_fh);
    cudaGetSymbolAddress((void**)&pwq2, g_wq2);
    cudaGetSymbolAddress((void**)&pwkv1, g_wkv1);
    cudaGetSymbolAddress((void**)&pwkv2, g_wkv2);
    cudaGetSymbolAddress((void**)&pwkv3, g_wkv3);
    cudaGetSymbolAddress((void**)&pw12, g_w12);
    cudaGetSymbolAddress((void**)&pw22, g_w22);

    cudaFuncSetAttribute(mma_gemm, cudaFuncAttributeMaxDynamicSharedMemorySize, GSMEM_TOTAL);
    cudaFuncSetAttribute(mma_gemm_kv, cudaFuncAttributeMaxDynamicSharedMemorySize, GSMEM_TOTAL);

    const long long sND = (long long)NN * DD;
    const long long sDD = (long long)DD * DD;
    const int stype[RR] = {1, 2, 3, 1};
    const int GMX = (NN + 127) / 128;   // 391
    const int CW = (DD * DD + 255) / 256;

    // launches 0-2: prereqs; launch index 3 = fused Q GEMM (profiled)
    {
        long long total = (long long)TT * NN * DD;
        half_a_kernel<<<(unsigned)((total + 255) / 256), 256>>>(x, px2, total);        // 0
    }
    half_w_kernel<<<CW, 256>>>(Wq + 0 * sDD, pwq2 + 0LL * sDD, DD, DD);                // 1
    half_w_kernel<<<CW, 256>>>(Wq + 3 * sDD, pwq2 + 3LL * sDD, DD, DD);                // 2
    {
        // fused Q projections for dst types 0 and 3: z in {0,1}, stride 3x
        dim3 g(GMX, DD / 128, 2);
        mma_gemm<<<g, 256, GSMEM_TOTAL>>>(px2, pwq2, bq, pQ, nullptr,                  // 3
                                          NN, DD, DD,
                                          3LL * sND, 3LL * sDD, 3LL * DD, 3LL * sND, 0);
    }

    // weight folds
    for (int r = 0; r < RR; r++) {
        combine_w_kernel<<<CW, 256>>>(Wk, W_attn, pWkr + (long long)r * sDD, stype[r], r);
        combine_w_kernel<<<CW, 256>>>(Wv, W_msg, pWvr + (long long)r * sDD, stype[r], r);
    }
    combine_b_kernel<<<1, DD>>>(bk, W_attn, pbkv1 + 0,   stype[0], 0);
    combine_b_kernel<<<1, DD>>>(bv, W_msg,  pbkv1 + 256, stype[0], 0);
    combine_b_kernel<<<1, DD>>>(bk, W_attn, pbkv1 + 512, stype[3], 3);
    combine_b_kernel<<<1, DD>>>(bv, W_msg,  pbkv1 + 768, stype[3], 3);
    combine_b_kernel<<<1, DD>>>(bk, W_attn, pbkv2 + 0,   stype[1], 1);
    combine_b_kernel<<<1, DD>>>(bv, W_msg,  pbkv2 + 256, stype[1], 1);
    combine_b_kernel<<<1, DD>>>(bk, W_attn, pbkv3 + 0,   stype[2], 2);
    combine_b_kernel<<<1, DD>>>(bv, W_msg,  pbkv3 + 256, stype[2], 2);
    // fp16 weights into concatenated buffers
    half_w_kernel<<<CW, 256>>>(pWkr + 0LL * sDD, pwkv1 + 0LL   * DD, DD, DD);  // r0 k
    half_w_kernel<<<CW, 256>>>(pWvr + 0LL * sDD, pwkv1 + 256LL * DD, DD, DD);  // r0 v
    half_w_kernel<<<CW, 256>>>(pWkr + 3LL * sDD, pwkv1 + 512LL * DD, DD, DD);  // r3 k
    half_w_kernel<<<CW, 256>>>(pWvr + 3LL * sDD, pwkv1 + 768LL * DD, DD, DD);  // r3 v
    half_w_kernel<<<CW, 256>>>(pWkr + 1LL * sDD, pwkv2 + 0LL   * DD, DD, DD);  // r1 k
    half_w_kernel<<<CW, 256>>>(pWvr + 1LL * sDD, pwkv2 + 256LL * DD, DD, DD);  // r1 v
    half_w_kernel<<<CW, 256>>>(pWkr + 2LL * sDD, pwkv3 + 0LL   * DD, DD, DD);  // r2 k
    half_w_kernel<<<CW, 256>>>(pWvr + 2LL * sDD, pwkv3 + 256LL * DD, DD, DD);  // r2 v
    for (int t = 0; t < TT; t++) {
        half_w_kernel<<<(DD * D4 + 255) / 256, 256>>>(ffn_w1 + (long long)t * DD * D4,
                                                      pw12 + (long long)t * D4 * DD, DD, D4);
        half_w_kernel<<<(D4 * DD + 255) / 256, 256>>>(ffn_w2 + (long long)t * D4 * DD,
                                                      pw22 + (long long)t * DD * D4, D4, DD);
    }

    // fused KV GEMMs (all three source types, one launch)
    {
        KVSegs segs;
        segs.A[0] = px2 + 1LL * sND; segs.B[0] = pwkv1; segs.bias[0] = pbkv1;
        segs.C[0] = pkv1; segs.N[0] = 1024; segs.nshift[0] = 3; segs.start[0] = 0;
        segs.A[1] = px2 + 2LL * sND; segs.B[1] = pwkv2; segs.bias[1] = pbkv2;
        segs.C[1] = pkv2; segs.N[1] = 512;  segs.nshift[1] = 2; segs.start[1] = GMX * 8;
        segs.A[2] = px2 + 3LL * sND; segs.B[2] = pwkv3; segs.bias[2] = pbkv3;
        segs.C[2] = pkv3; segs.N[2] = 512;  segs.nshift[2] = 2; segs.start[2] = GMX * 12;
        mma_gemm_kv<<<GMX * 16, 256, GSMEM_TOTAL>>>(segs);
    }

    // edge phase (all relations in one pass)
    cudaMemsetAsync(pagg, 0, sizeof(float) * TT * NN * DD, 0);
    cudaMemsetAsync(pm, 0, sizeof(unsigned) * RR * NN * HH, 0);
    cudaMemsetAsync(pz, 0, sizeof(float) * RR * NN * HH, 0);
    {
        long long ne = (long long)RR * EE;
        edge_dot_all<<<(unsigned)((ne + 7) / 8), 256>>>(pQ, pkv1, pkv2, pkv3, esrc, edst, relbias);
        long long nh = ne * HH;
        seg_exp_all<<<(unsigned)((nh + 255) / 256), 256>>>(edst);
        recip_z_kernel<<<(RR * NN * HH + 255) / 256, 256>>>();
        long long nm = ne * 64;
        seg_msg_all<<<(unsigned)((nm + 255) / 256), 256>>>(esrc, edst, pkv1, pkv2, pkv3, pagg);
    }

    // h = LN1(x + agg) (+ fp16 h2)
    ln_kernel<<<(TT * NN + 7) / 8, 256>>>(x, pagg, ln1_g, ln1_b, ph, ph2);

    // FFN1: fh = fp16(gelu(h @ W1 + b1))
    {
        dim3 g(GMX, D4 / 128, TT);
        mma_gemm<<<g, 256, GSMEM_TOTAL>>>(ph2, pw12, ffn_b1, nullptr, pfh,
                                          NN, DD, D4,
                                          sND, (long long)D4 * DD,
                                          D4, (long long)NN * D4, 1);
    }
    // FFN2: f2 = fh @ W2 + b2
    {
        dim3 g(GMX, DD / 128, TT);
        mma_gemm<<<g, 256, GSMEM_TOTAL>>>(pfh, pw22, ffn_b2, pf2, nullptr,
                                          NN, D4, DD,
                                          (long long)NN * D4, (long long)DD * D4,
                                          DD, sND, 0);
    }

    // out = LN2(h + f2)
    ln_kernel<<<(TT * NN + 7) / 8, 256>>>(ph, pf2, ln2_g, ln2_b, out, nullptr);

    (void)in_sizes; (void)n_in; (void)out_size;
}

// round 17
// speedup vs baseline: 1.5437x; 1.0188x over previous
#include <cuda_runtime.h>
#include <cuda_fp16.h>
#include <math.h>
#include <stdint.h>

#define TT 4
#define NN 50000
#define DD 256
#define HH 8
#define RR 4
#define EE 200000
#define DK 32
#define D4 1024

// ---------------- scratch (device globals; allocation is forbidden) ----------------
__device__ __align__(16) __half   g_Q2[(size_t)TT*NN*DD];     // fp16 Q (types 0,3 used)
__device__ __align__(16) __half   g_kv1[(size_t)NN*1024];     // fp16 st=1: [k_r0|v_r0|k_r3|v_r3]
__device__ __align__(16) __half   g_kv2[(size_t)NN*512];      // fp16 st=2: [k_r1|v_r1]
__device__ __align__(16) __half   g_kv3[(size_t)NN*512];      // fp16 st=3: [k_r2|v_r2]
__device__ __align__(16) float    g_agg[(size_t)TT*NN*DD];
__device__ __align__(16) float    g_h[(size_t)TT*NN*DD];
__device__ __align__(16) float    g_f2[(size_t)TT*NN*DD];
__device__ __align__(16) float    g_logits[(size_t)RR*EE*HH];
__device__ __align__(16) float    g_p[(size_t)RR*EE*HH];
__device__ __align__(16) unsigned g_m[(size_t)RR*NN*HH];
__device__ __align__(16) float    g_z[(size_t)RR*NN*HH];
__device__ __align__(16) float    g_Wkr[RR*DD*DD];
__device__ __align__(16) float    g_Wvr[RR*DD*DD];
__device__ __align__(16) float    g_bkv1[1024];
__device__ __align__(16) float    g_bkv2[512];
__device__ __align__(16) float    g_bkv3[512];
// pure-fp16 GEMM operands
__device__ __align__(256) __half g_x2[(size_t)TT*NN*DD];
__device__ __align__(256) __half g_h2[(size_t)TT*NN*DD];
__device__ __align__(256) __half g_fh[(size_t)TT*NN*D4];
__device__ __align__(256) __half g_wq2[(size_t)TT*DD*DD];
__device__ __align__(256) __half g_wkv1[(size_t)1024*DD];
__device__ __align__(256) __half g_wkv2[(size_t)512*DD];
__device__ __align__(256) __half g_wkv3[(size_t)512*DD];
__device__ __align__(256) __half g_w12[(size_t)TT*D4*DD];
__device__ __align__(256) __half g_w22[(size_t)TT*DD*D4];

// ---------------- small helpers ----------------
__device__ __forceinline__ unsigned fenc(float f) {
    unsigned u = __float_as_uint(f);
    return (u & 0x80000000u) ? ~u : (u | 0x80000000u);
}
__device__ __forceinline__ float fdec(unsigned u) {
    unsigned b = (u & 0x80000000u) ? (u & 0x7FFFFFFFu) : ~u;
    return __uint_as_float(b);
}
__device__ __forceinline__ uint32_t smem_u32(const void* p) {
    return (uint32_t)__cvta_generic_to_shared(p);
}
__device__ __forceinline__ void cp16(uint32_t d, const void* g, int sz) {
    asm volatile("cp.async.cg.shared.global [%0], [%1], 16, %2;"
                 :: "r"(d), "l"(g), "r"(sz));
}
__device__ __forceinline__ void cp_commit() {
    asm volatile("cp.async.commit_group;");
}
__device__ __forceinline__ void ldm_x4(uint32_t* r, uint32_t a) {
    asm volatile("ldmatrix.sync.aligned.m8n8.x4.shared.b16 {%0,%1,%2,%3}, [%4];"
                 : "=r"(r[0]), "=r"(r[1]), "=r"(r[2]), "=r"(r[3]) : "r"(a));
}
__device__ __forceinline__ void mma16816(float* c, const uint32_t* a,
                                         uint32_t b0, uint32_t b1) {
    asm volatile(
        "mma.sync.aligned.m16n8k16.row.col.f32.f16.f16.f32 "
        "{%0,%1,%2,%3}, {%4,%5,%6,%7}, {%8,%9}, {%0,%1,%2,%3};"
        : "+f"(c[0]), "+f"(c[1]), "+f"(c[2]), "+f"(c[3])
        : "r"(a[0]), "r"(a[1]), "r"(a[2]), "r"(a[3]), "r"(b0), "r"(b1));
}

// ---------------- fp16 GEMM core (software-pipelined fragments) ----------------
// epi: 0 = fp32 out, 1 = gelu + fp16 out, 2 = plain fp16 out
#define ROWB 80
#define STAGE_B (128*ROWB*2)
#define GSMEM_TOTAL (4*STAGE_B)

__device__ __forceinline__ void gemm_core(
    const __half* __restrict__ A2, const __half* __restrict__ B2,
    const float* __restrict__ bias, float* __restrict__ Cout,
    __half* __restrict__ C2out, int M, int K2, int Nout,
    int bm, int bn, char* smem, int epi)
{
    const uint32_t sb = smem_u32(smem);
    const int tid = threadIdx.x;
    const int wid = tid >> 5;
    const int lane = tid & 31;
    const int wm = wid >> 2;
    const int wn = wid & 3;
    const int NC = K2 >> 5;

    const int crow = tid >> 2;
    const int cc4  = tid & 3;
    const __half* srcA0 = A2 + (long long)(bm + crow) * K2 + cc4 * 8;
    const __half* srcA1 = srcA0 + (long long)64 * K2;
    const __half* srcB0 = B2 + (long long)(bn + crow) * K2 + cc4 * 8;
    const __half* srcB1 = srcB0 + (long long)64 * K2;
    const int szA0 = (bm + crow      < M) ? 16 : 0;
    const int szA1 = (bm + crow + 64 < M) ? 16 : 0;
    const uint32_t dA0 = sb + crow * ROWB + cc4 * 16;
    const uint32_t dA1 = dA0 + 64 * ROWB;
    const uint32_t dB0 = dA0 + 128 * ROWB;
    const uint32_t dB1 = dB0 + 64 * ROWB;

    uint32_t a_ld[4], b_ld[2];
    {
        int col2 = ((lane >> 4) << 4);
        #pragma unroll
        for (int mi = 0; mi < 4; mi++)
            a_ld[mi] = sb + (wm * 64 + mi * 16 + (lane & 15)) * ROWB + col2;
        #pragma unroll
        for (int bi = 0; bi < 2; bi++)
            b_ld[bi] = sb + 128 * ROWB + (wn * 32 + bi * 16 + (lane & 15)) * ROWB + col2;
    }

    float acc[4][4][4];
#pragma unroll
    for (int i = 0; i < 4; i++)
#pragma unroll
        for (int j = 0; j < 4; j++)
#pragma unroll
            for (int c = 0; c < 4; c++) acc[i][j][c] = 0.f;

    uint32_t wo = 0;
#define LOADN do {                                                \
        cp16(dA0 + wo, srcA0, szA0); cp16(dA1 + wo, srcA1, szA1); \
        cp16(dB0 + wo, srcB0, 16);   cp16(dB1 + wo, srcB1, 16);   \
        cp_commit();                                              \
        srcA0 += 32; srcA1 += 32; srcB0 += 32; srcB1 += 32;       \
        wo += STAGE_B; if (wo == 4 * STAGE_B) wo = 0;             \
    } while (0)

    LOADN; LOADN; LOADN;

    uint32_t ro = 0;
    for (int j = 0; j < NC; j++) {
        int wg = NC - 1 - j; if (wg > 2) wg = 2;
        if (wg == 2)      asm volatile("cp.async.wait_group 2;");
        else if (wg == 1) asm volatile("cp.async.wait_group 1;");
        else              asm volatile("cp.async.wait_group 0;");
        __syncthreads();
        if (j + 3 < NC) LOADN;

        uint32_t bfr[2][2][4];
#pragma unroll
        for (int kh = 0; kh < 2; kh++)
#pragma unroll
            for (int bi = 0; bi < 2; bi++)
                ldm_x4(bfr[kh][bi], b_ld[bi] + ro + kh * 32);
        uint32_t afr[4][4];
#pragma unroll
        for (int mi = 0; mi < 4; mi++) ldm_x4(afr[mi], a_ld[mi] + ro);
#pragma unroll
        for (int mi = 0; mi < 4; mi++)
#pragma unroll
            for (int ni = 0; ni < 4; ni++)
                mma16816(acc[mi][ni], afr[mi],
                         bfr[0][ni >> 1][ni & 1], bfr[0][ni >> 1][(ni & 1) + 2]);
#pragma unroll
        for (int mi = 0; mi < 4; mi++) ldm_x4(afr[mi], a_ld[mi] + ro + 32);
#pragma unroll
        for (int mi = 0; mi < 4; mi++)
#pragma unroll
            for (int ni = 0; ni < 4; ni++)
                mma16816(acc[mi][ni], afr[mi],
                         bfr[1][ni >> 1][ni & 1], bfr[1][ni >> 1][(ni & 1) + 2]);

        ro += STAGE_B; if (ro == 4 * STAGE_B) ro = 0;
    }
#undef LOADN

#pragma unroll
    for (int mi = 0; mi < 4; mi++) {
#pragma unroll
        for (int half = 0; half < 2; half++) {
            int row = bm + wm * 64 + mi * 16 + (lane >> 2) + half * 8;
            if (row >= M) continue;
#pragma unroll
            for (int ni = 0; ni < 4; ni++) {
                int col = bn + wn * 32 + ni * 8 + ((lane & 3) << 1);
                float v0 = acc[mi][ni][half * 2 + 0] + bias[col + 0];
                float v1 = acc[mi][ni][half * 2 + 1] + bias[col + 1];
                if (epi == 0) {
                    float2 v = make_float2(v0, v1);
                    *(float2*)&Cout[(long long)row * Nout + col] = v;
                } else {
                    if (epi == 1) {
                        v0 = 0.5f * v0 * (1.f + erff(v0 * 0.7071067811865476f));
                        v1 = 0.5f * v1 * (1.f + erff(v1 * 0.7071067811865476f));
                    }
                    __half2 hp;
                    hp.x = __float2half_rn(v0);
                    hp.y = __float2half_rn(v1);
                    *(__half2*)&C2out[(long long)row * Nout + col] = hp;
                }
            }
        }
    }
}

// generic strided-batch GEMM
__global__ void __launch_bounds__(256, 2)
mma_gemm(const __half* __restrict__ A2, const __half* __restrict__ B2,
         const float* __restrict__ bias, float* __restrict__ Cout,
         __half* __restrict__ C2out,
         int M, int K2, int Nout,
         long long sA, long long sB, long long sBias, long long sC, int epi)
{
    extern __shared__ __align__(128) char smem[];
    const int t = blockIdx.z;
    gemm_core(A2 + (long long)t * sA, B2 + (long long)t * sB,
              bias + (long long)t * sBias,
              Cout ? Cout + (long long)t * sC : nullptr,
              C2out ? C2out + (long long)t * sC : nullptr,
              M, K2, Nout, blockIdx.x * 128, blockIdx.y * 128, smem, epi);
}

// fused KV GEMM: 3 segments, K=DD, M=NN, fp16 out
struct KVSegs {
    const __half* A[3];
    const __half* B[3];
    const float*  bias[3];
    __half*       C[3];
    int N[3];
    int nshift[3];
    int start[3];
};

__global__ void __launch_bounds__(256, 2)
mma_gemm_kv(KVSegs segs)
{
    extern __shared__ __align__(128) char smem[];
    int b = blockIdx.x;
    int s = (b >= segs.start[2]) ? 2 : (b >= segs.start[1]) ? 1 : 0;
    int local = b - segs.start[s];
    int nb_mask = (1 << segs.nshift[s]) - 1;
    int bm = (local >> segs.nshift[s]) * 128;
    int bn = (local & nb_mask) * 128;
    gemm_core(segs.A[s], segs.B[s], segs.bias[s], nullptr, segs.C[s],
              NN, DD, segs.N[s], bm, bn, smem, 2);
}

// ---------------- weight fold (fp32) ----------------
__global__ void __launch_bounds__(256)
combine_w_kernel(const float* __restrict__ W, const float* __restrict__ Wrel,
                 float* __restrict__ outW, int st, int r)
{
    int idx = blockIdx.x * 256 + threadIdx.x;
    if (idx >= DD * DD) return;
    int d = idx >> 8;
    int c = idx & 255;
    int h = c >> 5, f = c & 31;
    const float* wrow = W + ((long long)st * DD + d) * DD + h * DK;
    const float* wr   = Wrel + ((long long)(r * HH + h) * DK) * DK + f;
    float s = 0.f;
#pragma unroll
    for (int k = 0; k < DK; k++) s = fmaf(wrow[k], wr[k * DK], s);
    outW[idx] = s;
}

__global__ void
combine_b_kernel(const float* __restrict__ b, const float* __restrict__ Wrel,
                 float* __restrict__ outb, int st, int r)
{
    int c = blockIdx.x * blockDim.x + threadIdx.x;
    if (c >= DD) return;
    int h = c >> 5, f = c & 31;
    const float* br = b + st * DD + h * DK;
    const float* wr = Wrel + ((long long)(r * HH + h) * DK) * DK + f;
    float s = 0.f;
#pragma unroll
    for (int k = 0; k < DK; k++) s = fmaf(br[k], wr[k * DK], s);
    outb[c] = s;
}

// ---------------- fp16 conversions ----------------
__global__ void __launch_bounds__(256)
half_a_kernel(const float* __restrict__ A, __half* __restrict__ A2, long long total)
{
    long long i = (long long)blockIdx.x * 256 + threadIdx.x;
    if (i >= total) return;
    A2[i] = __float2half_rn(A[i]);
}

// W[K][Nw] -> W2[Nw][K] (transpose)
__global__ void __launch_bounds__(256)
half_w_kernel(const float* __restrict__ W, __half* __restrict__ W2,
              int K, int Nw)
{
    int i = blockIdx.x * 256 + threadIdx.x;
    if (i >= K * Nw) return;
    int k = i / Nw, n = i - k * Nw;
    W2[(long long)n * K + k] = __float2half_rn(W[i]);
}

// ---------------- merged edge phase across all relations (fp16 gathers) ----------------
__device__ __constant__ int c_dt[RR]    = {0, 0, 3, 3};
__device__ __constant__ int c_pitch[RR] = {1024, 512, 512, 1024};
__device__ __constant__ int c_koff[RR]  = {0, 0, 0, 512};
__device__ __constant__ int c_voff[RR]  = {256, 256, 256, 768};

__device__ __forceinline__ const __half* kv_base(int r, const __half* kv1,
                                                 const __half* kv2, const __half* kv3) {
    return (r == 1) ? kv2 : (r == 2) ? kv3 : kv1;
}

__global__ void __launch_bounds__(256)
edge_dot_all(const __half* __restrict__ Q, const __half* __restrict__ kv1,
             const __half* __restrict__ kv2, const __half* __restrict__ kv3,
             const int* __restrict__ esrc, const int* __restrict__ edst,
             const float* __restrict__ rel_bias)
{
    const int warp = threadIdx.x >> 5;
    const int lane = threadIdx.x & 31;
    const int h = lane >> 2, q = lane & 3;
    long long ge = (long long)blockIdx.x * 8 + warp;
    if (ge >= (long long)RR * EE) return;
    int r = (int)(ge / EE);
    int s = esrc[ge];
    int d = edst[ge];
    const __half* kb = kv_base(r, kv1, kv2, kv3);
    // 8 halves (16B) of Q and K per lane
    uint4 qv = *(const uint4*)&Q[((long long)c_dt[r] * NN + d) * DD + h * DK + q * 8];
    uint4 kv = *(const uint4*)&kb[(long long)s * c_pitch[r] + c_koff[r] + h * DK + q * 8];
    float acc = 0.f;
    const __half2* qh = (const __half2*)&qv;
    const __half2* kh2 = (const __half2*)&kv;
#pragma unroll
    for (int i = 0; i < 4; i++) {
        float2 qf = __half22float2(qh[i]);
        float2 kf = __half22float2(kh2[i]);
        acc = fmaf(qf.x, kf.x, acc);
        acc = fmaf(qf.y, kf.y, acc);
    }
    acc += __shfl_xor_sync(0xffffffffu, acc, 1);
    acc += __shfl_xor_sync(0xffffffffu, acc, 2);
    if (q == 0) {
        float lg = acc * 0.17677669529663687f + rel_bias[r];
        g_logits[ge * HH + h] = lg;
        atomicMax(&g_m[((long long)r * NN + d) * HH + h], fenc(lg));
    }
}

__global__ void __launch_bounds__(256)
seg_exp_all(const int* __restrict__ edst)
{
    long long i = (long long)blockIdx.x * 256 + threadIdx.x;
    if (i >= (long long)RR * EE * HH) return;
    long long ge = i >> 3;
    int h = (int)(i & 7);
    int r = (int)(ge / EE);
    int d = edst[ge];
    long long mz = ((long long)r * NN + d) * HH + h;
    float m = fdec(g_m[mz]);
    float p = expf(g_logits[i] - m);
    g_p[i] = p;
    atomicAdd(&g_z[mz], p);
}

__global__ void __launch_bounds__(256)
recip_z_kernel()
{
    int i = blockIdx.x * 256 + threadIdx.x;
    if (i >= RR * NN * HH) return;
    float z = g_z[i];
    g_z[i] = (z != 0.f) ? (1.f / z) : 0.f;
}

__global__ void __launch_bounds__(256)
seg_msg_all(const int* __restrict__ esrc, const int* __restrict__ edst,
            const __half* __restrict__ kv1, const __half* __restrict__ kv2,
            const __half* __restrict__ kv3, float* __restrict__ agg)
{
    long long i = (long long)blockIdx.x * 256 + threadIdx.x;   // RR*EE*64
    if (i >= (long long)RR * EE * 64) return;
    long long ge = i >> 6;
    int c = (int)(i & 63) * 4;
    int h = c >> 5;
    int r = (int)(ge / EE);
    int s = esrc[ge];
    int d = edst[ge];
    float attn = g_p[ge * HH + h] * g_z[((long long)r * NN + d) * HH + h];
    const __half* vb = kv_base(r, kv1, kv2, kv3);
    uint2 vv = *(const uint2*)&vb[(long long)s * c_pitch[r] + c_voff[r] + c];
    float2 f01 = __half22float2(((const __half2*)&vv)[0]);
    float2 f23 = __half22float2(((const __half2*)&vv)[1]);
    float* dst = &agg[((long long)c_dt[r] * NN + d) * DD + c];
    asm volatile("red.global.add.v4.f32 [%0], {%1,%2,%3,%4};"
                 :: "l"(dst), "f"(attn * f01.x), "f"(attn * f01.y),
                    "f"(attn * f23.x), "f"(attn * f23.y)
                 : "memory");
}

// ---------------- layernorm(residual) [+ optional fp16 out] ----------------
__global__ void __launch_bounds__(256)
ln_kernel(const float* __restrict__ X, const float* __restrict__ Res,
          const float* __restrict__ G, const float* __restrict__ B,
          float* __restrict__ Out, __half* __restrict__ Out2)
{
    int row = blockIdx.x * 8 + (threadIdx.x >> 5);
    if (row >= TT * NN) return;
    int lane = threadIdx.x & 31;
    int t = row / NN;
    const float* xr = X + (long long)row * DD;
    const float* rr = Res + (long long)row * DD;
    float v[8];
    float sum = 0.f;
#pragma unroll
    for (int j = 0; j < 8; j++) {
        v[j] = xr[lane + 32 * j] + rr[lane + 32 * j];
        sum += v[j];
    }
#pragma unroll
    for (int o = 16; o > 0; o >>= 1) sum += __shfl_xor_sync(0xffffffffu, sum, o);
    float mu = sum * (1.f / 256.f);
    float var = 0.f;
#pragma unroll
    for (int j = 0; j < 8; j++) {
        float dlt = v[j] - mu;
        var = fmaf(dlt, dlt, var);
    }
#pragma unroll
    for (int o = 16; o > 0; o >>= 1) var += __shfl_xor_sync(0xffffffffu, var, o);
    float rstd = rsqrtf(var * (1.f / 256.f) + 1e-5f);
#pragma unroll
    for (int j = 0; j < 8; j++) {
        int c = lane + 32 * j;
        float y = (v[j] - mu) * rstd * G[t * DD + c] + B[t * DD + c];
        Out[(long long)row * DD + c] = y;
        if (Out2) Out2[(long long)row * DD + c] = __float2half_rn(y);
    }
}

// ---------------- launch ----------------
extern "C" void kernel_launch(void* const* d_in, const int* in_sizes, int n_in,
                              void* d_out, int out_size)
{
    const float* x       = (const float*)d_in[0];
    const int*   esrc    = (const int*)d_in[1];
    const int*   edst    = (const int*)d_in[2];
    const float* Wq      = (const float*)d_in[3];
    const float* bq      = (const float*)d_in[4];
    const float* Wk      = (const float*)d_in[5];
    const float* bk      = (const float*)d_in[6];
    const float* Wv      = (const float*)d_in[7];
    const float* bv      = (const float*)d_in[8];
    const float* W_attn  = (const float*)d_in[9];
    const float* W_msg   = (const float*)d_in[10];
    const float* relbias = (const float*)d_in[11];
    const float* ln1_g   = (const float*)d_in[12];
    const float* ln1_b   = (const float*)d_in[13];
    const float* ln2_g   = (const float*)d_in[14];
    const float* ln2_b   = (const float*)d_in[15];
    const float* ffn_w1  = (const float*)d_in[16];
    const float* ffn_b1  = (const float*)d_in[17];
    const float* ffn_w2  = (const float*)d_in[18];
    const float* ffn_b2  = (const float*)d_in[19];
    float* out = (float*)d_out;

    float *pagg, *ph, *pf2, *pz;
    float *pWkr, *pWvr, *pbkv1, *pbkv2, *pbkv3;
    unsigned* pm;
    __half *pQ2, *pkv1, *pkv2, *pkv3;
    __half *px2, *ph2, *pfh, *pwq2, *pwkv1, *pwkv2, *pwkv3, *pw12, *pw22;
    cudaGetSymbolAddress((void**)&pQ2, g_Q2);
    cudaGetSymbolAddress((void**)&pkv1, g_kv1);
    cudaGetSymbolAddress((void**)&pkv2, g_kv2);
    cudaGetSymbolAddress((void**)&pkv3, g_kv3);
    cudaGetSymbolAddress((void**)&pagg, g_agg);
    cudaGetSymbolAddress((void**)&ph, g_h);
    cudaGetSymbolAddress((void**)&pf2, g_f2);
    cudaGetSymbolAddress((void**)&pm, g_m);
    cudaGetSymbolAddress((void**)&pz, g_z);
    cudaGetSymbolAddress((void**)&pWkr, g_Wkr);
    cudaGetSymbolAddress((void**)&pWvr, g_Wvr);
    cudaGetSymbolAddress((void**)&pbkv1, g_bkv1);
    cudaGetSymbolAddress((void**)&pbkv2, g_bkv2);
    cudaGetSymbolAddress((void**)&pbkv3, g_bkv3);
    cudaGetSymbolAddress((void**)&px2, g_x2);
    cudaGetSymbolAddress((void**)&ph2, g_h2);
    cudaGetSymbolAddress((void**)&pfh, g_fh);
    cudaGetSymbolAddress((void**)&pwq2, g_wq2);
    cudaGetSymbolAddress((void**)&pwkv1, g_wkv1);
    cudaGetSymbolAddress((void**)&pwkv2, g_wkv2);
    cudaGetSymbolAddress((void**)&pwkv3, g_wkv3);
    cudaGetSymbolAddress((void**)&pw12, g_w12);
    cudaGetSymbolAddress((void**)&pw22, g_w22);

    cudaFuncSetAttribute(mma_gemm, cudaFuncAttributeMaxDynamicSharedMemorySize, GSMEM_TOTAL);
    cudaFuncSetAttribute(mma_gemm_kv, cudaFuncAttributeMaxDynamicSharedMemorySize, GSMEM_TOTAL);

    const long long sND = (long long)NN * DD;
    const long long sDD = (long long)DD * DD;
    const int stype[RR] = {1, 2, 3, 1};
    const int GMX = (NN + 127) / 128;   // 391
    const int CW = (DD * DD + 255) / 256;

    // launches 0-2: prereqs; launch index 3 = fused Q GEMM (profiled)
    {
        long long total = (long long)TT * NN * DD;
        half_a_kernel<<<(unsigned)((total + 255) / 256), 256>>>(x, px2, total);        // 0
    }
    half_w_kernel<<<CW, 256>>>(Wq + 0 * sDD, pwq2 + 0LL * sDD, DD, DD);                // 1
    half_w_kernel<<<CW, 256>>>(Wq + 3 * sDD, pwq2 + 3LL * sDD, DD, DD);                // 2
    {
        // fused Q projections (types 0,3) -> fp16 Q
        dim3 g(GMX, DD / 128, 2);
        mma_gemm<<<g, 256, GSMEM_TOTAL>>>(px2, pwq2, bq, nullptr, pQ2,                 // 3
                                          NN, DD, DD,
                                          3LL * sND, 3LL * sDD, 3LL * DD, 3LL * sND, 2);
    }

    // weight folds
    for (int r = 0; r < RR; r++) {
        combine_w_kernel<<<CW, 256>>>(Wk, W_attn, pWkr + (long long)r * sDD, stype[r], r);
        combine_w_kernel<<<CW, 256>>>(Wv, W_msg, pWvr + (long long)r * sDD, stype[r], r);
    }
    combine_b_kernel<<<1, DD>>>(bk, W_attn, pbkv1 + 0,   stype[0], 0);
    combine_b_kernel<<<1, DD>>>(bv, W_msg,  pbkv1 + 256, stype[0], 0);
    combine_b_kernel<<<1, DD>>>(bk, W_attn, pbkv1 + 512, stype[3], 3);
    combine_b_kernel<<<1, DD>>>(bv, W_msg,  pbkv1 + 768, stype[3], 3);
    combine_b_kernel<<<1, DD>>>(bk, W_attn, pbkv2 + 0,   stype[1], 1);
    combine_b_kernel<<<1, DD>>>(bv, W_msg,  pbkv2 + 256, stype[1], 1);
    combine_b_kernel<<<1, DD>>>(bk, W_attn, pbkv3 + 0,   stype[2], 2);
    combine_b_kernel<<<1, DD>>>(bv, W_msg,  pbkv3 + 256, stype[2], 2);
    // fp16 weights into concatenated buffers
    half_w_kernel<<<CW, 256>>>(pWkr + 0LL * sDD, pwkv1 + 0LL   * DD, DD, DD);  // r0 k
    half_w_kernel<<<CW, 256>>>(pWvr + 0LL * sDD, pwkv1 + 256LL * DD, DD, DD);  // r0 v
    half_w_kernel<<<CW, 256>>>(pWkr + 3LL * sDD, pwkv1 + 512LL * DD, DD, DD);  // r3 k
    half_w_kernel<<<CW, 256>>>(pWvr + 3LL * sDD, pwkv1 + 768LL * DD, DD, DD);  // r3 v
    half_w_kernel<<<CW, 256>>>(pWkr + 1LL * sDD, pwkv2 + 0LL   * DD, DD, DD);  // r1 k
    half_w_kernel<<<CW, 256>>>(pWvr + 1LL * sDD, pwkv2 + 256LL * DD, DD, DD);  // r1 v
    half_w_kernel<<<CW, 256>>>(pWkr + 2LL * sDD, pwkv3 + 0LL   * DD, DD, DD);  // r2 k
    half_w_kernel<<<CW, 256>>>(pWvr + 2LL * sDD, pwkv3 + 256LL * DD, DD, DD);  // r2 v
    for (int t = 0; t < TT; t++) {
        half_w_kernel<<<(DD * D4 + 255) / 256, 256>>>(ffn_w1 + (long long)t * DD * D4,
                                                      pw12 + (long long)t * D4 * DD, DD, D4);
        half_w_kernel<<<(D4 * DD + 255) / 256, 256>>>(ffn_w2 + (long long)t * D4 * DD,
                                                      pw22 + (long long)t * DD * D4, D4, DD);
    }

    // fused KV GEMMs (all three source types, fp16 out)
    {
        KVSegs segs;
        segs.A[0] = px2 + 1LL * sND; segs.B[0] = pwkv1; segs.bias[0] = pbkv1;
        segs.C[0] = pkv1; segs.N[0] = 1024; segs.nshift[0] = 3; segs.start[0] = 0;
        segs.A[1] = px2 + 2LL * sND; segs.B[1] = pwkv2; segs.bias[1] = pbkv2;
        segs.C[1] = pkv2; segs.N[1] = 512;  segs.nshift[1] = 2; segs.start[1] = GMX * 8;
        segs.A[2] = px2 + 3LL * sND; segs.B[2] = pwkv3; segs.bias[2] = pbkv3;
        segs.C[2] = pkv3; segs.N[2] = 512;  segs.nshift[2] = 2; segs.start[2] = GMX * 12;
        mma_gemm_kv<<<GMX * 16, 256, GSMEM_TOTAL>>>(segs);
    }

    // edge phase (all relations in one pass)
    cudaMemsetAsync(pagg, 0, sizeof(float) * TT * NN * DD, 0);
    cudaMemsetAsync(pm, 0, sizeof(unsigned) * RR * NN * HH, 0);
    cudaMemsetAsync(pz, 0, sizeof(float) * RR * NN * HH, 0);
    {
        long long ne = (long long)RR * EE;
        edge_dot_all<<<(unsigned)((ne + 7) / 8), 256>>>(pQ2, pkv1, pkv2, pkv3, esrc, edst, relbias);
        long long nh = ne * HH;
        seg_exp_all<<<(unsigned)((nh + 255) / 256), 256>>>(edst);
        recip_z_kernel<<<(RR * NN * HH + 255) / 256, 256>>>();
        long long nm = ne * 64;
        seg_msg_all<<<(unsigned)((nm + 255) / 256), 256>>>(esrc, edst, pkv1, pkv2, pkv3, pagg);
    }

    // h = LN1(x + agg) (+ fp16 h2)
    ln_kernel<<<(TT * NN + 7) / 8, 256>>>(x, pagg, ln1_g, ln1_b, ph, ph2);

    // FFN1: fh = fp16(gelu(h @ W1 + b1))
    {
        dim3 g(GMX, D4 / 128, TT);
        mma_gemm<<<g, 256, GSMEM_TOTAL>>>(ph2, pw12, ffn_b1, nullptr, pfh,
                                          NN, DD, D4,
                                          sND, (long long)D4 * DD,
                                          D4, (long long)NN * D4, 1);
    }
    // FFN2: f2 = fh @ W2 + b2
    {
        dim3 g(GMX, DD / 128, TT);
        mma_gemm<<<g, 256, GSMEM_TOTAL>>>(pfh, pw22, ffn_b2, pf2, nullptr,
                                          NN, D4, DD,
                                          (long long)NN * D4, (long long)DD * D4,
                                          DD, sND, 0);
    }

    // out = LN2(h + f2)
    ln_kernel<<<(TT * NN + 7) / 8, 256>>>(ph, pf2, ln2_g, ln2_b, out, nullptr);

    (void)in_sizes; (void)n_in; (void)out_size;
}